// round 7
// baseline (speedup 1.0000x reference)
#include <cuda_runtime.h>
#include <cuda_bf16.h>
#include <cstdint>
#include <math.h>

#define T_TOK 4096
#define H_DIM 1024
#define F_DIM 2048
#define E_NUM 8
#define F2    (2 * F_DIM)

// ===================== helpers =====================
__device__ __forceinline__ uint32_t smem_u32(const void* p) {
    uint32_t a;
    asm("{ .reg .u64 t; cvta.to.shared.u64 t, %1; cvt.u32.u64 %0, t; }" : "=r"(a) : "l"(p));
    return a;
}
#define SW128(off) ((off) ^ (((off) >> 3) & 0x70))

__device__ __forceinline__ void cp_async16(uint32_t dst, const void* src, int srcBytes) {
    asm volatile("cp.async.cg.shared.global [%0], [%1], 16, %2;"
                 :: "r"(dst), "l"(src), "r"(srcBytes) : "memory");
}
#define CP_COMMIT() asm volatile("cp.async.commit_group;" ::: "memory")
#define CP_WAIT(n)  asm volatile("cp.async.wait_group %0;" :: "n"(n) : "memory")

__device__ __forceinline__ void ldsm4(uint32_t* r, uint32_t addr) {
    asm volatile("ldmatrix.sync.aligned.m8n8.x4.shared.b16 {%0,%1,%2,%3}, [%4];"
                 : "=r"(r[0]), "=r"(r[1]), "=r"(r[2]), "=r"(r[3]) : "r"(addr));
}

__device__ __forceinline__ void mma16816(float* d, const uint32_t* a, uint32_t b0, uint32_t b1) {
    asm volatile("mma.sync.aligned.m16n8k16.row.col.f32.bf16.bf16.f32 "
                 "{%0,%1,%2,%3}, {%4,%5,%6,%7}, {%8,%9}, {%0,%1,%2,%3};"
                 : "+f"(d[0]), "+f"(d[1]), "+f"(d[2]), "+f"(d[3])
                 : "r"(a[0]), "r"(a[1]), "r"(a[2]), "r"(a[3]), "r"(b0), "r"(b1));
}

__device__ __forceinline__ uint32_t pack_bf16(float x, float y) {
    __nv_bfloat162 t;
    t.x = __float2bfloat16(x);
    t.y = __float2bfloat16(y);
    return *(uint32_t*)&t;
}

// ===================== scratch =====================
__device__ __nv_bfloat16 g_x_hi [(size_t)T_TOK * H_DIM];
__device__ __nv_bfloat16 g_x_lo [(size_t)T_TOK * H_DIM];
__device__ __nv_bfloat16 g_sw1t_hi[(size_t)2 * F_DIM * H_DIM];
__device__ __nv_bfloat16 g_sw1t_lo[(size_t)2 * F_DIM * H_DIM];
__device__ __nv_bfloat16 g_ew1t_hi[(size_t)E_NUM * F_DIM * H_DIM];
__device__ __nv_bfloat16 g_ew1t_lo[(size_t)E_NUM * F_DIM * H_DIM];
__device__ __nv_bfloat16 g_sw2t_hi[(size_t)H_DIM * F2];
__device__ __nv_bfloat16 g_sw2t_lo[(size_t)H_DIM * F2];
__device__ __nv_bfloat16 g_ew2t_hi[(size_t)E_NUM * H_DIM * F_DIM];
__device__ __nv_bfloat16 g_ew2t_lo[(size_t)E_NUM * H_DIM * F_DIM];
__device__ __nv_bfloat16 g_hids_hi[(size_t)T_TOK * F2];
__device__ __nv_bfloat16 g_hids_lo[(size_t)T_TOK * F2];
__device__ __nv_bfloat16 g_hidr_hi[(size_t)2 * T_TOK * F_DIM];
__device__ __nv_bfloat16 g_hidr_lo[(size_t)2 * T_TOK * F_DIM];
__device__ float g_rout[(size_t)2 * T_TOK * H_DIM];
__device__ int g_counts[E_NUM];
__device__ int g_base[E_NUM];
__device__ int g_list[E_NUM * T_TOK];
__device__ int g_tok_e[2 * T_TOK];
__device__ int g_tok_slot[2 * T_TOK];

// ===================== small kernels =====================
__global__ void zero_kernel() {
    if (threadIdx.x < E_NUM) g_counts[threadIdx.x] = 0;
}

__global__ void router_kernel(const float* __restrict__ x,
                              const float* __restrict__ rw,
                              const float* __restrict__ rb) {
    int warp = (blockIdx.x * blockDim.x + threadIdx.x) >> 5;
    int lane = threadIdx.x & 31;
    if (warp >= T_TOK) return;
    const float* xp = x + (long)warp * H_DIM;
    float acc[E_NUM];
#pragma unroll
    for (int e = 0; e < E_NUM; e++) acc[e] = 0.f;
    for (int h = lane; h < H_DIM; h += 32) {
        float xv = xp[h];
        const float* w = rw + (long)h * E_NUM;
#pragma unroll
        for (int e = 0; e < E_NUM; e++) acc[e] = fmaf(xv, w[e], acc[e]);
    }
#pragma unroll
    for (int e = 0; e < E_NUM; e++)
#pragma unroll
        for (int off = 16; off; off >>= 1)
            acc[e] += __shfl_xor_sync(0xFFFFFFFFu, acc[e], off);
    if (lane == 0) {
        float lg[E_NUM];
#pragma unroll
        for (int e = 0; e < E_NUM; e++) lg[e] = acc[e] + rb[e];
        int e0 = 0;
#pragma unroll
        for (int e = 1; e < E_NUM; e++) if (lg[e] > lg[e0]) e0 = e;
        int e1 = -1;
#pragma unroll
        for (int e = 0; e < E_NUM; e++) {
            if (e == e0) continue;
            if (e1 < 0 || lg[e] > lg[e1]) e1 = e;
        }
        int sel[2] = { e0, e1 };
        int t = warp;
#pragma unroll
        for (int k = 0; k < 2; k++) {
            int e = sel[k];
            int slot = atomicAdd(&g_counts[e], 1);
            g_list[e * T_TOK + slot] = t;
            g_tok_e[2 * t + k] = e;
            g_tok_slot[2 * t + k] = slot;
        }
    }
}

__global__ void base_kernel() {
    if (threadIdx.x == 0) {
        int s = 0;
#pragma unroll
        for (int e = 0; e < E_NUM; e++) { g_base[e] = s; s += g_counts[e]; }
    }
}

__global__ void combine_kernel(float* __restrict__ out) {
    int t = blockIdx.x;
    int e0 = g_tok_e[2 * t], e1 = g_tok_e[2 * t + 1];
    long r0 = (long)g_base[e0] + g_tok_slot[2 * t];
    long r1 = (long)g_base[e1] + g_tok_slot[2 * t + 1];
    const float4* p0 = (const float4*)g_rout + r0 * (H_DIM / 4);
    const float4* p1 = (const float4*)g_rout + r1 * (H_DIM / 4);
    float4* op = (float4*)out + (long)t * (H_DIM / 4);
    int i = threadIdx.x;
    float4 o = op[i], a = p0[i], b = p1[i];
    o.x += a.x + b.x; o.y += a.y + b.y; o.z += a.z + b.z; o.w += a.w + b.w;
    op[i] = o;
}

// ===================== converters =====================
__global__ void split_kernel(const float* __restrict__ in,
                             __nv_bfloat16* __restrict__ hi,
                             __nv_bfloat16* __restrict__ lo, int n4) {
    int i = blockIdx.x * blockDim.x + threadIdx.x;
    if (i >= n4) return;
    float4 v = ((const float4*)in)[i];
    union { __nv_bfloat16 b[4]; uint2 u; } hb, lb;
    float vv[4] = { v.x, v.y, v.z, v.w };
#pragma unroll
    for (int u = 0; u < 4; u++) {
        __nv_bfloat16 h = __float2bfloat16(vv[u]);
        hb.b[u] = h;
        lb.b[u] = __float2bfloat16(vv[u] - __bfloat162float(h));
    }
    ((uint2*)hi)[i] = hb.u;
    ((uint2*)lo)[i] = lb.u;
}

__global__ void tsplitG1(const float* __restrict__ sw1, const float* __restrict__ ew1) {
    __shared__ float t[32][33];
    int z = blockIdx.z;
    const float* src;
    __nv_bfloat16 *hi, *lo;
    if (z < E_NUM) {
        src = ew1 + (size_t)z * H_DIM * F_DIM;
        hi = g_ew1t_hi + (size_t)z * F_DIM * H_DIM;
        lo = g_ew1t_lo + (size_t)z * F_DIM * H_DIM;
    } else {
        int n = z - E_NUM;
        src = sw1 + (size_t)n * H_DIM * F_DIM;
        hi = g_sw1t_hi + (size_t)n * F_DIM * H_DIM;
        lo = g_sw1t_lo + (size_t)n * F_DIM * H_DIM;
    }
    int n0 = blockIdx.x * 32, k0 = blockIdx.y * 32;
    int tx = threadIdx.x, ty = threadIdx.y;
#pragma unroll
    for (int i = 0; i < 32; i += 8)
        t[ty + i][tx] = src[(long)(k0 + ty + i) * F_DIM + n0 + tx];
    __syncthreads();
#pragma unroll
    for (int i = 0; i < 32; i += 8) {
        float v = t[tx][ty + i];
        __nv_bfloat16 h = __float2bfloat16(v);
        long o = (long)(n0 + ty + i) * H_DIM + k0 + tx;
        hi[o] = h;
        lo[o] = __float2bfloat16(v - __bfloat162float(h));
    }
}

__global__ void tsplitG2(const float* __restrict__ sw2, const float* __restrict__ ew2) {
    __shared__ float t[32][33];
    int z = blockIdx.z;
    const float* src;
    __nv_bfloat16 *hi, *lo;
    long obase; int ld;
    if (z < E_NUM) {
        src = ew2 + (size_t)z * F_DIM * H_DIM;
        hi = g_ew2t_hi; lo = g_ew2t_lo;
        obase = (size_t)z * H_DIM * F_DIM; ld = F_DIM;
    } else {
        int n = z - E_NUM;
        src = sw2 + (size_t)n * F_DIM * H_DIM;
        hi = g_sw2t_hi; lo = g_sw2t_lo;
        obase = (long)n * F_DIM; ld = F2;
    }
    int n0 = blockIdx.x * 32, k0 = blockIdx.y * 32;
    int tx = threadIdx.x, ty = threadIdx.y;
#pragma unroll
    for (int i = 0; i < 32; i += 8)
        t[ty + i][tx] = src[(long)(k0 + ty + i) * H_DIM + n0 + tx];
    __syncthreads();
#pragma unroll
    for (int i = 0; i < 32; i += 8) {
        float v = t[tx][ty + i];
        __nv_bfloat16 h = __float2bfloat16(v);
        long o = obase + (long)(n0 + ty + i) * ld + k0 + tx;
        hi[o] = h;
        lo[o] = __float2bfloat16(v - __bfloat162float(h));
    }
}

// ===================== GEMM core: CTA 256x128, 256 thr, warp 64x64 ==========
// Per BK=32 chunk, 128B rows hold [hi k0..31 | lo k0..31].
// Stage = A 32KB + B 16KB = 48KB; 3 stages; prefetch depth 2.
#define STAGE_BYTES 49152
#define B_OFF 32768
#define DSMEM_BYTES (3 * STAGE_BYTES)

template<bool GELU>
__device__ __forceinline__ void gemm_core(
    const __nv_bfloat16* __restrict__ Ahi, const __nv_bfloat16* __restrict__ Alo,
    const __nv_bfloat16* __restrict__ Bhi, const __nv_bfloat16* __restrict__ Blo,
    const float* __restrict__ bias, const float* __restrict__ bias2,
    __nv_bfloat16* Chi, __nv_bfloat16* Clo, float* Cf,
    int M, int K, int ldc, int colOff, const int* list, int rowBase)
{
    int colBase = blockIdx.y * 128;
    extern __shared__ char smem[];
    uint32_t sbase = smem_u32(smem);
    int tid = threadIdx.x;
    int wid = tid >> 5, lane = tid & 31;
    int warpM = wid & 3, warpN = wid >> 2;   // 4 x 2

    // ---- loader metadata ----
    int c = tid & 7;                 // 16B column in 128B row
    int r0 = tid >> 3;               // 0..31
    bool hiSel = c < 4;
    int kel = (c & 3) * 8;
    uint32_t swBaseA = SW128((uint32_t)(r0 * 128 + c * 16));
    uint32_t swBaseB = B_OFF + swBaseA;
    const __nv_bfloat16* Ap = hiSel ? Ahi : Alo;
    const __nv_bfloat16* Bp = hiSel ? Bhi : Blo;

    const __nv_bfloat16* aSrc[8];
    uint32_t aOkMask = 0;
#pragma unroll
    for (int i = 0; i < 8; i++) {
        int gR = rowBase + r0 + 32 * i;
        bool ok = gR < M;
        if (ok) aOkMask |= (1u << i);
        int rrow = list ? (ok ? list[gR] : 0) : (ok ? gR : 0);
        aSrc[i] = Ap + (long)rrow * K + kel;
    }
    const __nv_bfloat16* bSrc[4];
#pragma unroll
    for (int j = 0; j < 4; j++)
        bSrc[j] = Bp + (long)(colBase + r0 + 32 * j) * K + kel;

    const int NC = K >> 5;
    auto issue = [&](int ci) {
        uint32_t st = sbase + (ci % 3) * STAGE_BYTES;
        int kbase = ci << 5;
#pragma unroll
        for (int i = 0; i < 8; i++)
            cp_async16(st + swBaseA + 4096u * i, aSrc[i] + kbase,
                       (aOkMask >> i) & 1 ? 16 : 0);
#pragma unroll
        for (int j = 0; j < 4; j++)
            cp_async16(st + swBaseB + 4096u * j, bSrc[j] + kbase, 16);
        CP_COMMIT();
    };

    float acc[4][8][4];
#pragma unroll
    for (int mi = 0; mi < 4; mi++)
#pragma unroll
        for (int nj = 0; nj < 8; nj++)
#pragma unroll
            for (int u = 0; u < 4; u++) acc[mi][nj][u] = 0.f;

    int lrow = lane & 15;
    int lc16 = (lane >> 4) * 16;
    uint32_t swA[4], swB[4];
#pragma unroll
    for (int mi = 0; mi < 4; mi++)
        swA[mi] = SW128((uint32_t)((warpM * 64 + mi * 16 + lrow) * 128 + lc16));
#pragma unroll
    for (int g = 0; g < 4; g++)
        swB[g] = B_OFF + SW128((uint32_t)((warpN * 64 + g * 16 + lrow) * 128 + lc16));

    issue(0); issue(1);
    for (int ci = 0; ci < NC; ci++) {
        CP_WAIT(1);
        __syncthreads();
        if (ci + 2 < NC) issue(ci + 2);
        else CP_COMMIT();
        uint32_t st = sbase + (ci % 3) * STAGE_BYTES;
#pragma unroll
        for (int ks = 0; ks < 2; ks++) {
            uint32_t koff = ks * 32;
            uint32_t ah[4][4], al[4][4];
#pragma unroll
            for (int mi = 0; mi < 4; mi++) {
                ldsm4(ah[mi], st + (swA[mi] ^ koff));
                ldsm4(al[mi], st + (swA[mi] ^ (koff + 64)));
            }
#pragma unroll
            for (int g = 0; g < 4; g++) {
                uint32_t bh[4], bl[4];
                ldsm4(bh, st + (swB[g] ^ koff));
                ldsm4(bl, st + (swB[g] ^ (koff + 64)));
#pragma unroll
                for (int mi = 0; mi < 4; mi++) {
                    mma16816(acc[mi][2 * g + 0], ah[mi], bh[0], bh[2]);
                    mma16816(acc[mi][2 * g + 1], ah[mi], bh[1], bh[3]);
                    mma16816(acc[mi][2 * g + 0], al[mi], bh[0], bh[2]);
                    mma16816(acc[mi][2 * g + 1], al[mi], bh[1], bh[3]);
                    mma16816(acc[mi][2 * g + 0], ah[mi], bl[0], bl[2]);
                    mma16816(acc[mi][2 * g + 1], ah[mi], bl[1], bl[3]);
                }
            }
        }
        __syncthreads();
    }

    // epilogue
    int rw0 = rowBase + warpM * 64 + (lane >> 2);
    int cw0 = colBase + warpN * 64 + (lane & 3) * 2;
#pragma unroll
    for (int mi = 0; mi < 4; mi++) {
#pragma unroll
        for (int nj = 0; nj < 8; nj++) {
            int col = cw0 + nj * 8;
            float b0 = bias[col], b1 = bias[col + 1];
            if (bias2) { b0 += bias2[col]; b1 += bias2[col + 1]; }
#pragma unroll
            for (int h = 0; h < 2; h++) {
                int row_ = rw0 + mi * 16 + h * 8;
                if (row_ < M) {
                    float v0 = acc[mi][nj][2 * h + 0] + b0;
                    float v1 = acc[mi][nj][2 * h + 1] + b1;
                    long off = (long)row_ * ldc + colOff + col;
                    if (GELU) {
                        float g0 = 0.5f * v0 * (1.0f + erff(v0 * 0.70710678118654752f));
                        float g1 = 0.5f * v1 * (1.0f + erff(v1 * 0.70710678118654752f));
                        float h0 = __bfloat162float(__float2bfloat16(g0));
                        float h1 = __bfloat162float(__float2bfloat16(g1));
                        *(uint32_t*)(Chi + off) = pack_bf16(g0, g1);
                        *(uint32_t*)(Clo + off) = pack_bf16(g0 - h0, g1 - h1);
                    } else {
                        float2 v; v.x = v0; v.y = v1;
                        *(float2*)(Cf + off) = v;
                    }
                }
            }
        }
    }
}

// GEMM1: z<8 routed expert z (gather); z>=8 shared n=z-8. zBase selects subrange.
__global__ __launch_bounds__(256, 1)
void moe_gemm1(const __nv_bfloat16* __restrict__ x_hi,
               const __nv_bfloat16* __restrict__ x_lo,
               const float* __restrict__ sb1, const float* __restrict__ eb1,
               int zBase)
{
    int z = blockIdx.z + zBase;
    int M, ldc, colOff;
    const int* list;
    const __nv_bfloat16 *Bh, *Bl;
    const float* bias;
    __nv_bfloat16 *Ch, *Cl;
    if (z < E_NUM) {
        M = g_counts[z];
        list = g_list + (long)z * T_TOK;
        Bh = g_ew1t_hi + (size_t)z * F_DIM * H_DIM;
        Bl = g_ew1t_lo + (size_t)z * F_DIM * H_DIM;
        bias = eb1 + z * F_DIM;
        long b = g_base[z];
        Ch = g_hidr_hi + b * (long)F_DIM;
        Cl = g_hidr_lo + b * (long)F_DIM;
        ldc = F_DIM; colOff = 0;
    } else {
        int n = z - E_NUM;
        M = T_TOK;
        list = nullptr;
        Bh = g_sw1t_hi + (size_t)n * F_DIM * H_DIM;
        Bl = g_sw1t_lo + (size_t)n * F_DIM * H_DIM;
        bias = sb1 + n * F_DIM;
        Ch = g_hids_hi; Cl = g_hids_lo;
        ldc = F2; colOff = n * F_DIM;
    }
    int rowBase = blockIdx.x * 256;
    if (rowBase >= M) return;
    gemm_core<true>(x_hi, x_lo, Bh, Bl, bias, nullptr,
                    Ch, Cl, nullptr, M, H_DIM, ldc, colOff, list, rowBase);
}

// GEMM2: z<8 routed; z==8 shared (K=F2, writes out).
__global__ __launch_bounds__(256, 1)
void moe_gemm2(const float* __restrict__ sb2, const float* __restrict__ eb2,
               float* __restrict__ out)
{
    int z = blockIdx.z;
    int M, K;
    const __nv_bfloat16 *Ah, *Al, *Bh, *Bl;
    const float *bias, *bias2;
    float* Cf;
    if (z < E_NUM) {
        M = g_counts[z];
        long b = g_base[z];
        Ah = g_hidr_hi + b * (long)F_DIM;
        Al = g_hidr_lo + b * (long)F_DIM;
        K = F_DIM;
        Bh = g_ew2t_hi + (size_t)z * H_DIM * F_DIM;
        Bl = g_ew2t_lo + (size_t)z * H_DIM * F_DIM;
        bias = eb2 + z * H_DIM; bias2 = nullptr;
        Cf = g_rout + b * (long)H_DIM;
    } else {
        M = T_TOK;
        Ah = g_hids_hi; Al = g_hids_lo;
        K = F2;
        Bh = g_sw2t_hi; Bl = g_sw2t_lo;
        bias = sb2; bias2 = sb2 + H_DIM;
        Cf = out;
    }
    int rowBase = blockIdx.x * 256;
    if (rowBase >= M) return;
    gemm_core<false>(Ah, Al, Bh, Bl, bias, bias2,
                     nullptr, nullptr, Cf, M, K, H_DIM, 0, nullptr, rowBase);
}

// ===================== launch =====================
static void* symAddr(const void* sym) { void* p; cudaGetSymbolAddress(&p, sym); return p; }

extern "C" void kernel_launch(void* const* d_in, const int* in_sizes, int n_in,
                              void* d_out, int out_size)
{
    const float* x   = (const float*)d_in[0];
    const float* sw1 = (const float*)d_in[1];
    const float* sb1 = (const float*)d_in[2];
    const float* sw2 = (const float*)d_in[3];
    const float* sb2 = (const float*)d_in[4];
    const float* ew1 = (const float*)d_in[5];
    const float* eb1 = (const float*)d_in[6];
    const float* ew2 = (const float*)d_in[7];
    const float* eb2 = (const float*)d_in[8];
    const float* rw  = (const float*)d_in[9];
    const float* rb  = (const float*)d_in[10];
    float* out = (float*)d_out;

    __nv_bfloat16* x_hi = (__nv_bfloat16*)symAddr(g_x_hi);
    __nv_bfloat16* x_lo = (__nv_bfloat16*)symAddr(g_x_lo);

    cudaFuncSetAttribute(moe_gemm1, cudaFuncAttributeMaxDynamicSharedMemorySize, DSMEM_BYTES);
    cudaFuncSetAttribute(moe_gemm2, cudaFuncAttributeMaxDynamicSharedMemorySize, DSMEM_BYTES);

    // 1
    split_kernel<<<(T_TOK * H_DIM / 4 + 255) / 256, 256>>>(x, x_hi, x_lo, T_TOK * H_DIM / 4);
    // 2
    tsplitG1<<<dim3(F_DIM / 32, H_DIM / 32, E_NUM + 2), dim3(32, 8)>>>(sw1, ew1);
    // 3
    zero_kernel<<<1, 32>>>();
    // 4 (PROFILED): shared GEMM1 (no router dependency)
    moe_gemm1<<<dim3(T_TOK / 256, F_DIM / 128, 2), 256, DSMEM_BYTES>>>(
        x_hi, x_lo, sb1, eb1, E_NUM);
    // 5
    router_kernel<<<T_TOK / 4, 128>>>(x, rw, rb);
    // 6
    base_kernel<<<1, 32>>>();
    // 7: routed GEMM1
    moe_gemm1<<<dim3(T_TOK / 256, F_DIM / 128, E_NUM), 256, DSMEM_BYTES>>>(
        x_hi, x_lo, sb1, eb1, 0);
    // 8
    tsplitG2<<<dim3(H_DIM / 32, F_DIM / 32, E_NUM + 2), dim3(32, 8)>>>(sw2, ew2);
    // 9
    moe_gemm2<<<dim3(T_TOK / 256, H_DIM / 128, E_NUM + 1), 256, DSMEM_BYTES>>>(
        sb2, eb2, out);
    // 10
    combine_kernel<<<T_TOK, 256>>>(out);
}

// round 8
// speedup vs baseline: 1.1987x; 1.1987x over previous
#include <cuda_runtime.h>
#include <cuda_bf16.h>
#include <cstdint>
#include <math.h>

#define T_TOK 4096
#define H_DIM 1024
#define F_DIM 2048
#define E_NUM 8
#define F2    (2 * F_DIM)

// ===================== helpers =====================
__device__ __forceinline__ uint32_t smem_u32(const void* p) {
    uint32_t a;
    asm("{ .reg .u64 t; cvta.to.shared.u64 t, %1; cvt.u32.u64 %0, t; }" : "=r"(a) : "l"(p));
    return a;
}
#define SW128(off) ((off) ^ (((off) >> 3) & 0x70))

__device__ __forceinline__ void cp_async16(uint32_t dst, const void* src, int srcBytes) {
    asm volatile("cp.async.cg.shared.global [%0], [%1], 16, %2;"
                 :: "r"(dst), "l"(src), "r"(srcBytes) : "memory");
}
#define CP_COMMIT() asm volatile("cp.async.commit_group;" ::: "memory")
#define CP_WAIT0()  asm volatile("cp.async.wait_group 0;" ::: "memory")

__device__ __forceinline__ void ldsm4(uint32_t* r, uint32_t addr) {
    asm volatile("ldmatrix.sync.aligned.m8n8.x4.shared.b16 {%0,%1,%2,%3}, [%4];"
                 : "=r"(r[0]), "=r"(r[1]), "=r"(r[2]), "=r"(r[3]) : "r"(addr));
}

__device__ __forceinline__ void mma16816(float* d, const uint32_t* a, uint32_t b0, uint32_t b1) {
    asm volatile("mma.sync.aligned.m16n8k16.row.col.f32.bf16.bf16.f32 "
                 "{%0,%1,%2,%3}, {%4,%5,%6,%7}, {%8,%9}, {%0,%1,%2,%3};"
                 : "+f"(d[0]), "+f"(d[1]), "+f"(d[2]), "+f"(d[3])
                 : "r"(a[0]), "r"(a[1]), "r"(a[2]), "r"(a[3]), "r"(b0), "r"(b1));
}

__device__ __forceinline__ uint32_t pack_bf16(float x, float y) {
    __nv_bfloat162 t;
    t.x = __float2bfloat16(x);
    t.y = __float2bfloat16(y);
    return *(uint32_t*)&t;
}

// ===================== scratch =====================
__device__ __nv_bfloat16 g_x_hi [(size_t)T_TOK * H_DIM];
__device__ __nv_bfloat16 g_x_lo [(size_t)T_TOK * H_DIM];
__device__ __nv_bfloat16 g_sw1t_hi[(size_t)2 * F_DIM * H_DIM];
__device__ __nv_bfloat16 g_sw1t_lo[(size_t)2 * F_DIM * H_DIM];
__device__ __nv_bfloat16 g_ew1t_hi[(size_t)E_NUM * F_DIM * H_DIM];
__device__ __nv_bfloat16 g_ew1t_lo[(size_t)E_NUM * F_DIM * H_DIM];
__device__ __nv_bfloat16 g_sw2t_hi[(size_t)H_DIM * F2];
__device__ __nv_bfloat16 g_sw2t_lo[(size_t)H_DIM * F2];
__device__ __nv_bfloat16 g_ew2t_hi[(size_t)E_NUM * H_DIM * F_DIM];
__device__ __nv_bfloat16 g_ew2t_lo[(size_t)E_NUM * H_DIM * F_DIM];
__device__ __nv_bfloat16 g_hids_hi[(size_t)T_TOK * F2];
__device__ __nv_bfloat16 g_hids_lo[(size_t)T_TOK * F2];
__device__ __nv_bfloat16 g_hidr_hi[(size_t)2 * T_TOK * F_DIM];
__device__ __nv_bfloat16 g_hidr_lo[(size_t)2 * T_TOK * F_DIM];
__device__ float g_rout[(size_t)2 * T_TOK * H_DIM];
__device__ int g_counts[E_NUM];
__device__ int g_base[E_NUM];
__device__ int g_list[E_NUM * T_TOK];
__device__ int g_tok_e[2 * T_TOK];
__device__ int g_tok_slot[2 * T_TOK];

// ===================== small kernels =====================
__global__ void zero_kernel() {
    if (threadIdx.x < E_NUM) g_counts[threadIdx.x] = 0;
}

__global__ void router_kernel(const float* __restrict__ x,
                              const float* __restrict__ rw,
                              const float* __restrict__ rb) {
    int warp = (blockIdx.x * blockDim.x + threadIdx.x) >> 5;
    int lane = threadIdx.x & 31;
    if (warp >= T_TOK) return;
    const float* xp = x + (long)warp * H_DIM;
    float acc[E_NUM];
#pragma unroll
    for (int e = 0; e < E_NUM; e++) acc[e] = 0.f;
    for (int h = lane; h < H_DIM; h += 32) {
        float xv = xp[h];
        const float* w = rw + (long)h * E_NUM;
#pragma unroll
        for (int e = 0; e < E_NUM; e++) acc[e] = fmaf(xv, w[e], acc[e]);
    }
#pragma unroll
    for (int e = 0; e < E_NUM; e++)
#pragma unroll
        for (int off = 16; off; off >>= 1)
            acc[e] += __shfl_xor_sync(0xFFFFFFFFu, acc[e], off);
    if (lane == 0) {
        float lg[E_NUM];
#pragma unroll
        for (int e = 0; e < E_NUM; e++) lg[e] = acc[e] + rb[e];
        int e0 = 0;
#pragma unroll
        for (int e = 1; e < E_NUM; e++) if (lg[e] > lg[e0]) e0 = e;
        int e1 = -1;
#pragma unroll
        for (int e = 0; e < E_NUM; e++) {
            if (e == e0) continue;
            if (e1 < 0 || lg[e] > lg[e1]) e1 = e;
        }
        int sel[2] = { e0, e1 };
        int t = warp;
#pragma unroll
        for (int k = 0; k < 2; k++) {
            int e = sel[k];
            int slot = atomicAdd(&g_counts[e], 1);
            g_list[e * T_TOK + slot] = t;
            g_tok_e[2 * t + k] = e;
            g_tok_slot[2 * t + k] = slot;
        }
    }
}

__global__ void base_kernel() {
    if (threadIdx.x == 0) {
        int s = 0;
#pragma unroll
        for (int e = 0; e < E_NUM; e++) { g_base[e] = s; s += g_counts[e]; }
    }
}

__global__ void combine_kernel(float* __restrict__ out) {
    int t = blockIdx.x;
    int e0 = g_tok_e[2 * t], e1 = g_tok_e[2 * t + 1];
    long r0 = (long)g_base[e0] + g_tok_slot[2 * t];
    long r1 = (long)g_base[e1] + g_tok_slot[2 * t + 1];
    const float4* p0 = (const float4*)g_rout + r0 * (H_DIM / 4);
    const float4* p1 = (const float4*)g_rout + r1 * (H_DIM / 4);
    float4* op = (float4*)out + (long)t * (H_DIM / 4);
    int i = threadIdx.x;
    float4 o = op[i], a = p0[i], b = p1[i];
    o.x += a.x + b.x; o.y += a.y + b.y; o.z += a.z + b.z; o.w += a.w + b.w;
    op[i] = o;
}

// ===================== converters =====================
__global__ void split_kernel(const float* __restrict__ in,
                             __nv_bfloat16* __restrict__ hi,
                             __nv_bfloat16* __restrict__ lo, int n4) {
    int i = blockIdx.x * blockDim.x + threadIdx.x;
    if (i >= n4) return;
    float4 v = ((const float4*)in)[i];
    union { __nv_bfloat16 b[4]; uint2 u; } hb, lb;
    float vv[4] = { v.x, v.y, v.z, v.w };
#pragma unroll
    for (int u = 0; u < 4; u++) {
        __nv_bfloat16 h = __float2bfloat16(vv[u]);
        hb.b[u] = h;
        lb.b[u] = __float2bfloat16(vv[u] - __bfloat162float(h));
    }
    ((uint2*)hi)[i] = hb.u;
    ((uint2*)lo)[i] = lb.u;
}

__global__ void tsplitG1(const float* __restrict__ sw1, const float* __restrict__ ew1) {
    __shared__ float t[32][33];
    int z = blockIdx.z;
    const float* src;
    __nv_bfloat16 *hi, *lo;
    if (z < E_NUM) {
        src = ew1 + (size_t)z * H_DIM * F_DIM;
        hi = g_ew1t_hi + (size_t)z * F_DIM * H_DIM;
        lo = g_ew1t_lo + (size_t)z * F_DIM * H_DIM;
    } else {
        int n = z - E_NUM;
        src = sw1 + (size_t)n * H_DIM * F_DIM;
        hi = g_sw1t_hi + (size_t)n * F_DIM * H_DIM;
        lo = g_sw1t_lo + (size_t)n * F_DIM * H_DIM;
    }
    int n0 = blockIdx.x * 32, k0 = blockIdx.y * 32;
    int tx = threadIdx.x, ty = threadIdx.y;
#pragma unroll
    for (int i = 0; i < 32; i += 8)
        t[ty + i][tx] = src[(long)(k0 + ty + i) * F_DIM + n0 + tx];
    __syncthreads();
#pragma unroll
    for (int i = 0; i < 32; i += 8) {
        float v = t[tx][ty + i];
        __nv_bfloat16 h = __float2bfloat16(v);
        long o = (long)(n0 + ty + i) * H_DIM + k0 + tx;
        hi[o] = h;
        lo[o] = __float2bfloat16(v - __bfloat162float(h));
    }
}

__global__ void tsplitG2(const float* __restrict__ sw2, const float* __restrict__ ew2) {
    __shared__ float t[32][33];
    int z = blockIdx.z;
    const float* src;
    __nv_bfloat16 *hi, *lo;
    long obase; int ld;
    if (z < E_NUM) {
        src = ew2 + (size_t)z * F_DIM * H_DIM;
        hi = g_ew2t_hi; lo = g_ew2t_lo;
        obase = (size_t)z * H_DIM * F_DIM; ld = F_DIM;
    } else {
        int n = z - E_NUM;
        src = sw2 + (size_t)n * F_DIM * H_DIM;
        hi = g_sw2t_hi; lo = g_sw2t_lo;
        obase = (long)n * F_DIM; ld = F2;
    }
    int n0 = blockIdx.x * 32, k0 = blockIdx.y * 32;
    int tx = threadIdx.x, ty = threadIdx.y;
#pragma unroll
    for (int i = 0; i < 32; i += 8)
        t[ty + i][tx] = src[(long)(k0 + ty + i) * H_DIM + n0 + tx];
    __syncthreads();
#pragma unroll
    for (int i = 0; i < 32; i += 8) {
        float v = t[tx][ty + i];
        __nv_bfloat16 h = __float2bfloat16(v);
        long o = obase + (long)(n0 + ty + i) * ld + k0 + tx;
        hi[o] = h;
        lo[o] = __float2bfloat16(v - __bfloat162float(h));
    }
}

// ===================== GEMM core: CTA 64x64, 128 thr, warp 32x32 ==========
// 128B smem rows hold [hi k0..31 | lo k0..31]; stage = A 8KB + B 8KB = 16KB.
// 2 stages double-buffered, one __syncthreads per chunk.
#define STAGE_BYTES 16384
#define B_OFF 8192
#define DSMEM_BYTES (2 * STAGE_BYTES)

template<bool GELU>
__device__ __forceinline__ void gemm_core(
    const __nv_bfloat16* __restrict__ Ahi, const __nv_bfloat16* __restrict__ Alo,
    const __nv_bfloat16* __restrict__ Bhi, const __nv_bfloat16* __restrict__ Blo,
    const float* __restrict__ bias, const float* __restrict__ bias2,
    __nv_bfloat16* Chi, __nv_bfloat16* Clo, float* Cf,
    int M, int K, int ldc, int colOff, const int* list, int rowBase)
{
    int colBase = blockIdx.y * 64;
    extern __shared__ char smem[];
    uint32_t sbase = smem_u32(smem);
    int tid = threadIdx.x;
    int wid = tid >> 5, lane = tid & 31;
    int warpM = wid & 1, warpN = wid >> 1;   // 2 x 2 warps

    // ---- loader metadata (c constant across the 4 units per thread) ----
    int c = tid & 7;
    bool hiSel = c < 4;
    int kel = (c & 3) * 8;
    int r0 = tid >> 3;                         // 0..15
    uint32_t sw0 = SW128((uint32_t)(r0 * 128 + c * 16));
    const __nv_bfloat16* Ap = hiSel ? Ahi : Alo;
    const __nv_bfloat16* Bp = hiSel ? Bhi : Blo;
    int aRow[4]; uint32_t aOk = 0;
#pragma unroll
    for (int i = 0; i < 4; i++) {
        int gR = rowBase + r0 + 16 * i;
        bool ok = gR < M;
        if (ok) aOk |= (1u << i);
        aRow[i] = list ? (ok ? list[gR] : 0) : (ok ? gR : 0);
    }

    const int NC = K >> 5;
    auto issue = [&](int ci) {
        uint32_t st = sbase + (uint32_t)(ci & 1) * STAGE_BYTES;
        int kbase = ci << 5;
#pragma unroll
        for (int i = 0; i < 4; i++) {
            cp_async16(st + sw0 + 2048u * i,
                       Ap + (long)aRow[i] * K + kbase + kel,
                       (aOk >> i) & 1 ? 16 : 0);
            cp_async16(st + B_OFF + sw0 + 2048u * i,
                       Bp + (long)(colBase + r0 + 16 * i) * K + kbase + kel, 16);
        }
        CP_COMMIT();
    };

    float acc[2][4][4];
#pragma unroll
    for (int mi = 0; mi < 2; mi++)
#pragma unroll
        for (int nj = 0; nj < 4; nj++)
#pragma unroll
            for (int u = 0; u < 4; u++) acc[mi][nj][u] = 0.f;

    int lrow = lane & 15;
    int lc16 = (lane >> 4) * 16;
    uint32_t swA[2], swB[2];
#pragma unroll
    for (int mi = 0; mi < 2; mi++)
        swA[mi] = SW128((uint32_t)((warpM * 32 + mi * 16 + lrow) * 128 + lc16));
#pragma unroll
    for (int g = 0; g < 2; g++)
        swB[g] = B_OFF + SW128((uint32_t)((warpN * 32 + g * 16 + lrow) * 128 + lc16));

    issue(0);
    for (int ci = 0; ci < NC; ci++) {
        CP_WAIT0();
        __syncthreads();
        if (ci + 1 < NC) issue(ci + 1);
        uint32_t st = sbase + (uint32_t)(ci & 1) * STAGE_BYTES;
#pragma unroll
        for (int ks = 0; ks < 2; ks++) {
            uint32_t koff = ks * 32;
            uint32_t ah[2][4], al[2][4];
#pragma unroll
            for (int mi = 0; mi < 2; mi++) {
                ldsm4(ah[mi], st + (swA[mi] ^ koff));
                ldsm4(al[mi], st + (swA[mi] ^ (koff + 64)));
            }
#pragma unroll
            for (int g = 0; g < 2; g++) {
                uint32_t bh[4], bl[4];
                ldsm4(bh, st + (swB[g] ^ koff));
                ldsm4(bl, st + (swB[g] ^ (koff + 64)));
#pragma unroll
                for (int mi = 0; mi < 2; mi++) {
                    mma16816(acc[mi][2 * g + 0], ah[mi], bh[0], bh[2]);
                    mma16816(acc[mi][2 * g + 1], ah[mi], bh[1], bh[3]);
                    mma16816(acc[mi][2 * g + 0], al[mi], bh[0], bh[2]);
                    mma16816(acc[mi][2 * g + 1], al[mi], bh[1], bh[3]);
                    mma16816(acc[mi][2 * g + 0], ah[mi], bl[0], bl[2]);
                    mma16816(acc[mi][2 * g + 1], ah[mi], bl[1], bl[3]);
                }
            }
        }
    }

    // epilogue
    int rw0 = rowBase + warpM * 32 + (lane >> 2);
    int cw0 = colBase + warpN * 32 + (lane & 3) * 2;
#pragma unroll
    for (int mi = 0; mi < 2; mi++) {
#pragma unroll
        for (int nj = 0; nj < 4; nj++) {
            int col = cw0 + nj * 8;
            float b0 = bias[col], b1 = bias[col + 1];
            if (bias2) { b0 += bias2[col]; b1 += bias2[col + 1]; }
#pragma unroll
            for (int h = 0; h < 2; h++) {
                int row_ = rw0 + mi * 16 + h * 8;
                if (row_ < M) {
                    float v0 = acc[mi][nj][2 * h + 0] + b0;
                    float v1 = acc[mi][nj][2 * h + 1] + b1;
                    long off = (long)row_ * ldc + colOff + col;
                    if (GELU) {
                        float g0 = 0.5f * v0 * (1.0f + erff(v0 * 0.70710678118654752f));
                        float g1 = 0.5f * v1 * (1.0f + erff(v1 * 0.70710678118654752f));
                        float h0 = __bfloat162float(__float2bfloat16(g0));
                        float h1 = __bfloat162float(__float2bfloat16(g1));
                        *(uint32_t*)(Chi + off) = pack_bf16(g0, g1);
                        *(uint32_t*)(Clo + off) = pack_bf16(g0 - h0, g1 - h1);
                    } else {
                        float2 v; v.x = v0; v.y = v1;
                        *(float2*)(Cf + off) = v;
                    }
                }
            }
        }
    }
}

// GEMM1: z<8 routed expert z (gather); z>=8 shared n=z-8.
__global__ __launch_bounds__(128, 6)
void moe_gemm1(const __nv_bfloat16* __restrict__ x_hi,
               const __nv_bfloat16* __restrict__ x_lo,
               const float* __restrict__ sb1, const float* __restrict__ eb1,
               int zBase)
{
    int z = blockIdx.z + zBase;
    int M, ldc, colOff;
    const int* list;
    const __nv_bfloat16 *Bh, *Bl;
    const float* bias;
    __nv_bfloat16 *Ch, *Cl;
    if (z < E_NUM) {
        M = g_counts[z];
        list = g_list + (long)z * T_TOK;
        Bh = g_ew1t_hi + (size_t)z * F_DIM * H_DIM;
        Bl = g_ew1t_lo + (size_t)z * F_DIM * H_DIM;
        bias = eb1 + z * F_DIM;
        long b = g_base[z];
        Ch = g_hidr_hi + b * (long)F_DIM;
        Cl = g_hidr_lo + b * (long)F_DIM;
        ldc = F_DIM; colOff = 0;
    } else {
        int n = z - E_NUM;
        M = T_TOK;
        list = nullptr;
        Bh = g_sw1t_hi + (size_t)n * F_DIM * H_DIM;
        Bl = g_sw1t_lo + (size_t)n * F_DIM * H_DIM;
        bias = sb1 + n * F_DIM;
        Ch = g_hids_hi; Cl = g_hids_lo;
        ldc = F2; colOff = n * F_DIM;
    }
    int rowBase = blockIdx.x * 64;
    if (rowBase >= M) return;
    gemm_core<true>(x_hi, x_lo, Bh, Bl, bias, nullptr,
                    Ch, Cl, nullptr, M, H_DIM, ldc, colOff, list, rowBase);
}

// GEMM2: z<8 routed; z==8 shared (K=F2, writes out).
__global__ __launch_bounds__(128, 6)
void moe_gemm2(const float* __restrict__ sb2, const float* __restrict__ eb2,
               float* __restrict__ out)
{
    int z = blockIdx.z;
    int M, K;
    const __nv_bfloat16 *Ah, *Al, *Bh, *Bl;
    const float *bias, *bias2;
    float* Cf;
    if (z < E_NUM) {
        M = g_counts[z];
        long b = g_base[z];
        Ah = g_hidr_hi + b * (long)F_DIM;
        Al = g_hidr_lo + b * (long)F_DIM;
        K = F_DIM;
        Bh = g_ew2t_hi + (size_t)z * H_DIM * F_DIM;
        Bl = g_ew2t_lo + (size_t)z * H_DIM * F_DIM;
        bias = eb2 + z * H_DIM; bias2 = nullptr;
        Cf = g_rout + b * (long)H_DIM;
    } else {
        M = T_TOK;
        Ah = g_hids_hi; Al = g_hids_lo;
        K = F2;
        Bh = g_sw2t_hi; Bl = g_sw2t_lo;
        bias = sb2; bias2 = sb2 + H_DIM;
        Cf = out;
    }
    int rowBase = blockIdx.x * 64;
    if (rowBase >= M) return;
    gemm_core<false>(Ah, Al, Bh, Bl, bias, bias2,
                     nullptr, nullptr, Cf, M, K, H_DIM, 0, nullptr, rowBase);
}

// ===================== launch =====================
static void* symAddr(const void* sym) { void* p; cudaGetSymbolAddress(&p, sym); return p; }

extern "C" void kernel_launch(void* const* d_in, const int* in_sizes, int n_in,
                              void* d_out, int out_size)
{
    const float* x   = (const float*)d_in[0];
    const float* sw1 = (const float*)d_in[1];
    const float* sb1 = (const float*)d_in[2];
    const float* sw2 = (const float*)d_in[3];
    const float* sb2 = (const float*)d_in[4];
    const float* ew1 = (const float*)d_in[5];
    const float* eb1 = (const float*)d_in[6];
    const float* ew2 = (const float*)d_in[7];
    const float* eb2 = (const float*)d_in[8];
    const float* rw  = (const float*)d_in[9];
    const float* rb  = (const float*)d_in[10];
    float* out = (float*)d_out;

    __nv_bfloat16* x_hi = (__nv_bfloat16*)symAddr(g_x_hi);
    __nv_bfloat16* x_lo = (__nv_bfloat16*)symAddr(g_x_lo);

    cudaFuncSetAttribute(moe_gemm1, cudaFuncAttributeMaxDynamicSharedMemorySize, DSMEM_BYTES);
    cudaFuncSetAttribute(moe_gemm2, cudaFuncAttributeMaxDynamicSharedMemorySize, DSMEM_BYTES);

    // 1
    split_kernel<<<(T_TOK * H_DIM / 4 + 255) / 256, 256>>>(x, x_hi, x_lo, T_TOK * H_DIM / 4);
    // 2
    tsplitG1<<<dim3(F_DIM / 32, H_DIM / 32, E_NUM + 2), dim3(32, 8)>>>(sw1, ew1);
    // 3
    zero_kernel<<<1, 32>>>();
    // 4 (PROFILED): shared GEMM1
    moe_gemm1<<<dim3(T_TOK / 64, F_DIM / 64, 2), 128, DSMEM_BYTES>>>(
        x_hi, x_lo, sb1, eb1, E_NUM);
    // 5
    router_kernel<<<T_TOK / 4, 128>>>(x, rw, rb);
    // 6
    base_kernel<<<1, 32>>>();
    // 7: routed GEMM1
    moe_gemm1<<<dim3(T_TOK / 64, F_DIM / 64, E_NUM), 128, DSMEM_BYTES>>>(
        x_hi, x_lo, sb1, eb1, 0);
    // 8
    tsplitG2<<<dim3(H_DIM / 32, F_DIM / 32, E_NUM + 2), dim3(32, 8)>>>(sw2, ew2);
    // 9
    moe_gemm2<<<dim3(T_TOK / 64, H_DIM / 64, E_NUM + 1), 128, DSMEM_BYTES>>>(
        sb2, eb2, out);
    // 10
    combine_kernel<<<T_TOK, 256>>>(out);
}

// round 9
// speedup vs baseline: 1.5396x; 1.2844x over previous
#include <cuda_runtime.h>
#include <cuda_fp16.h>
#include <cstdint>
#include <math.h>

#define T_TOK 4096
#define H_DIM 1024
#define F_DIM 2048
#define E_NUM 8
#define F2    (2 * F_DIM)

// ===================== helpers =====================
__device__ __forceinline__ uint32_t smem_u32(const void* p) {
    uint32_t a;
    asm("{ .reg .u64 t; cvta.to.shared.u64 t, %1; cvt.u32.u64 %0, t; }" : "=r"(a) : "l"(p));
    return a;
}
#define SW128(off) ((off) ^ (((off) >> 3) & 0x70))

__device__ __forceinline__ void cp_async16(uint32_t dst, const void* src, int srcBytes) {
    asm volatile("cp.async.cg.shared.global [%0], [%1], 16, %2;"
                 :: "r"(dst), "l"(src), "r"(srcBytes) : "memory");
}
#define CP_COMMIT() asm volatile("cp.async.commit_group;" ::: "memory")
#define CP_WAIT0()  asm volatile("cp.async.wait_group 0;" ::: "memory")

__device__ __forceinline__ void ldsm4(uint32_t* r, uint32_t addr) {
    asm volatile("ldmatrix.sync.aligned.m8n8.x4.shared.b16 {%0,%1,%2,%3}, [%4];"
                 : "=r"(r[0]), "=r"(r[1]), "=r"(r[2]), "=r"(r[3]) : "r"(addr));
}

__device__ __forceinline__ void mma16816h(float* d, const uint32_t* a, uint32_t b0, uint32_t b1) {
    asm volatile("mma.sync.aligned.m16n8k16.row.col.f32.f16.f16.f32 "
                 "{%0,%1,%2,%3}, {%4,%5,%6,%7}, {%8,%9}, {%0,%1,%2,%3};"
                 : "+f"(d[0]), "+f"(d[1]), "+f"(d[2]), "+f"(d[3])
                 : "r"(a[0]), "r"(a[1]), "r"(a[2]), "r"(a[3]), "r"(b0), "r"(b1));
}

__device__ __forceinline__ uint32_t pack_h2(float x, float y) {
    __half2 t = __floats2half2_rn(x, y);
    return *(uint32_t*)&t;
}

// ===================== scratch =====================
__device__ __half g_x_hi [(size_t)T_TOK * H_DIM];
__device__ __half g_x_lo [(size_t)T_TOK * H_DIM];
__device__ __half g_sw1t [(size_t)2 * F_DIM * H_DIM];
__device__ __half g_ew1t [(size_t)E_NUM * F_DIM * H_DIM];
__device__ __half g_sw2t [(size_t)H_DIM * F2];
__device__ __half g_ew2t [(size_t)E_NUM * H_DIM * F_DIM];
__device__ __half g_hids_hi[(size_t)T_TOK * F2];
__device__ __half g_hids_lo[(size_t)T_TOK * F2];
__device__ __half g_hidr_hi[(size_t)2 * T_TOK * F_DIM];
__device__ __half g_hidr_lo[(size_t)2 * T_TOK * F_DIM];
__device__ float g_rout[(size_t)2 * T_TOK * H_DIM];
__device__ int g_counts[E_NUM];
__device__ int g_base[E_NUM];
__device__ int g_list[E_NUM * T_TOK];
__device__ int g_tok_e[2 * T_TOK];
__device__ int g_tok_slot[2 * T_TOK];

// ===================== small kernels =====================
__global__ void zero_kernel() {
    if (threadIdx.x < E_NUM) g_counts[threadIdx.x] = 0;
}

__global__ void router_kernel(const float* __restrict__ x,
                              const float* __restrict__ rw,
                              const float* __restrict__ rb) {
    int warp = (blockIdx.x * blockDim.x + threadIdx.x) >> 5;
    int lane = threadIdx.x & 31;
    if (warp >= T_TOK) return;
    const float* xp = x + (long)warp * H_DIM;
    float acc[E_NUM];
#pragma unroll
    for (int e = 0; e < E_NUM; e++) acc[e] = 0.f;
    for (int h = lane; h < H_DIM; h += 32) {
        float xv = xp[h];
        const float* w = rw + (long)h * E_NUM;
#pragma unroll
        for (int e = 0; e < E_NUM; e++) acc[e] = fmaf(xv, w[e], acc[e]);
    }
#pragma unroll
    for (int e = 0; e < E_NUM; e++)
#pragma unroll
        for (int off = 16; off; off >>= 1)
            acc[e] += __shfl_xor_sync(0xFFFFFFFFu, acc[e], off);
    if (lane == 0) {
        float lg[E_NUM];
#pragma unroll
        for (int e = 0; e < E_NUM; e++) lg[e] = acc[e] + rb[e];
        int e0 = 0;
#pragma unroll
        for (int e = 1; e < E_NUM; e++) if (lg[e] > lg[e0]) e0 = e;
        int e1 = -1;
#pragma unroll
        for (int e = 0; e < E_NUM; e++) {
            if (e == e0) continue;
            if (e1 < 0 || lg[e] > lg[e1]) e1 = e;
        }
        int sel[2] = { e0, e1 };
        int t = warp;
#pragma unroll
        for (int k = 0; k < 2; k++) {
            int e = sel[k];
            int slot = atomicAdd(&g_counts[e], 1);
            g_list[e * T_TOK + slot] = t;
            g_tok_e[2 * t + k] = e;
            g_tok_slot[2 * t + k] = slot;
        }
    }
}

__global__ void base_kernel() {
    if (threadIdx.x == 0) {
        int s = 0;
#pragma unroll
        for (int e = 0; e < E_NUM; e++) { g_base[e] = s; s += g_counts[e]; }
    }
}

__global__ void combine_kernel(float* __restrict__ out) {
    int t = blockIdx.x;
    int e0 = g_tok_e[2 * t], e1 = g_tok_e[2 * t + 1];
    long r0 = (long)g_base[e0] + g_tok_slot[2 * t];
    long r1 = (long)g_base[e1] + g_tok_slot[2 * t + 1];
    const float4* p0 = (const float4*)g_rout + r0 * (H_DIM / 4);
    const float4* p1 = (const float4*)g_rout + r1 * (H_DIM / 4);
    float4* op = (float4*)out + (long)t * (H_DIM / 4);
    int i = threadIdx.x;
    float4 o = op[i], a = p0[i], b = p1[i];
    o.x += a.x + b.x; o.y += a.y + b.y; o.z += a.z + b.z; o.w += a.w + b.w;
    op[i] = o;
}

// ===================== converters =====================
__global__ void split_kernel(const float* __restrict__ in,
                             __half* __restrict__ hi,
                             __half* __restrict__ lo, int n4) {
    int i = blockIdx.x * blockDim.x + threadIdx.x;
    if (i >= n4) return;
    float4 v = ((const float4*)in)[i];
    union { __half b[4]; uint2 u; } hb, lb;
    float vv[4] = { v.x, v.y, v.z, v.w };
#pragma unroll
    for (int u = 0; u < 4; u++) {
        __half h = __float2half_rn(vv[u]);
        hb.b[u] = h;
        lb.b[u] = __float2half_rn(vv[u] - __half2float(h));
    }
    ((uint2*)hi)[i] = hb.u;
    ((uint2*)lo)[i] = lb.u;
}

// w1 [H][F] per slice -> K-major [F][H] half (hi only). z<8: ew1[z]; else sw1[z-8].
__global__ void tsplitG1(const float* __restrict__ sw1, const float* __restrict__ ew1) {
    __shared__ float t[32][33];
    int z = blockIdx.z;
    const float* src;
    __half* hi;
    if (z < E_NUM) {
        src = ew1 + (size_t)z * H_DIM * F_DIM;
        hi = g_ew1t + (size_t)z * F_DIM * H_DIM;
    } else {
        int n = z - E_NUM;
        src = sw1 + (size_t)n * H_DIM * F_DIM;
        hi = g_sw1t + (size_t)n * F_DIM * H_DIM;
    }
    int n0 = blockIdx.x * 32, k0 = blockIdx.y * 32;
    int tx = threadIdx.x, ty = threadIdx.y;
#pragma unroll
    for (int i = 0; i < 32; i += 8)
        t[ty + i][tx] = src[(long)(k0 + ty + i) * F_DIM + n0 + tx];
    __syncthreads();
#pragma unroll
    for (int i = 0; i < 32; i += 8)
        hi[(long)(n0 + ty + i) * H_DIM + k0 + tx] = __float2half_rn(t[tx][ty + i]);
}

// w2 [F][H] per slice -> K-major half. z<8: ew2[z] ld=F; z>=8: sw2 into ld=F2 at col n*F.
__global__ void tsplitG2(const float* __restrict__ sw2, const float* __restrict__ ew2) {
    __shared__ float t[32][33];
    int z = blockIdx.z;
    const float* src;
    __half* hi;
    long obase; int ld;
    if (z < E_NUM) {
        src = ew2 + (size_t)z * F_DIM * H_DIM;
        hi = g_ew2t;
        obase = (size_t)z * H_DIM * F_DIM; ld = F_DIM;
    } else {
        int n = z - E_NUM;
        src = sw2 + (size_t)n * F_DIM * H_DIM;
        hi = g_sw2t;
        obase = (long)n * F_DIM; ld = F2;
    }
    int n0 = blockIdx.x * 32, k0 = blockIdx.y * 32;
    int tx = threadIdx.x, ty = threadIdx.y;
#pragma unroll
    for (int i = 0; i < 32; i += 8)
        t[ty + i][tx] = src[(long)(k0 + ty + i) * H_DIM + n0 + tx];
    __syncthreads();
#pragma unroll
    for (int i = 0; i < 32; i += 8)
        hi[obase + (long)(n0 + ty + i) * ld + k0 + tx] = __float2half_rn(t[tx][ty + i]);
}

// ===================== GEMM core: CTA 128x64, 128 thr, warp 64x32 ==========
// fp16 2-product: C = (Ah + Al) @ Bh^T.
// A stage: 128 rows x 128B = [Ah k0..31 (64B) | Al k0..31 (64B)] -> 16KB.
// B stage: 32 rows x 128B = [Bh[n=p] k0..31 | Bh[n=p+32] k0..31] -> 4KB.
// 2 stages, one __syncthreads per BK=32 chunk.
#define STAGE_BYTES 20480
#define B_OFF 16384
#define DSMEM_BYTES (2 * STAGE_BYTES)

template<bool GELU>
__device__ __forceinline__ void gemm_core(
    const __half* __restrict__ Ahi, const __half* __restrict__ Alo,
    const __half* __restrict__ Bh,
    const float* __restrict__ bias, const float* __restrict__ bias2,
    __half* Chi, __half* Clo, float* Cf,
    int M, int K, int ldc, int colOff, const int* list, int rowBase)
{
    int colBase = blockIdx.y * 64;
    extern __shared__ char smem[];
    uint32_t sbase = smem_u32(smem);
    int tid = threadIdx.x;
    int wid = tid >> 5, lane = tid & 31;
    int warpM = wid & 1, warpN = wid >> 1;   // 2 x 2 warps (64m x 32n each)

    // ---- loader metadata ----
    int c = tid & 7;                 // 16B chunk within 128B row
    bool hiSel = c < 4;
    int kel = (c & 3) * 8;           // fp16 elem offset within 32-wide chunk
    int r0 = tid >> 3;               // 0..15
    uint32_t swA0 = SW128((uint32_t)(r0 * 128 + c * 16));
    uint32_t swB0 = B_OFF + swA0;    // same pattern for B plane (p0 = r0)
    const __half* ApA = hiSel ? Ahi : Alo;
    // A rows: r0 + 16*i, i=0..7
    int aRow[8]; uint32_t aOk = 0;
#pragma unroll
    for (int i = 0; i < 8; i++) {
        int gR = rowBase + r0 + 16 * i;
        bool ok = gR < M;
        if (ok) aOk |= (1u << i);
        aRow[i] = list ? (ok ? list[gR] : 0) : (ok ? gR : 0);
    }
    // B units: p = r0 + 16*j (j=0..1), n = colBase + p + 32*(c>=4)
    int bN = colBase + r0 + (hiSel ? 0 : 32);

    const int NC = K >> 5;
    auto issue = [&](int ci) {
        uint32_t st = sbase + (uint32_t)(ci & 1) * STAGE_BYTES;
        int kbase = ci << 5;
#pragma unroll
        for (int i = 0; i < 8; i++)
            cp_async16(st + swA0 + 2048u * i,
                       ApA + (long)aRow[i] * K + kbase + kel,
                       (aOk >> i) & 1 ? 16 : 0);
#pragma unroll
        for (int j = 0; j < 2; j++)
            cp_async16(st + swB0 + 2048u * j,
                       Bh + (long)(bN + 16 * j) * K + kbase + kel, 16);
        CP_COMMIT();
    };

    float acc[4][4][4];
#pragma unroll
    for (int mi = 0; mi < 4; mi++)
#pragma unroll
        for (int nj = 0; nj < 4; nj++)
#pragma unroll
            for (int u = 0; u < 4; u++) acc[mi][nj][u] = 0.f;

    int lrow = lane & 15;
    int lc16 = (lane >> 4) * 16;
    uint32_t swA[4], swB[2];
#pragma unroll
    for (int mi = 0; mi < 4; mi++)
        swA[mi] = SW128((uint32_t)((warpM * 64 + mi * 16 + lrow) * 128 + lc16));
#pragma unroll
    for (int g = 0; g < 2; g++)
        swB[g] = B_OFF + SW128((uint32_t)((g * 16 + lrow) * 128 + warpN * 64 + lc16));

    issue(0);
    for (int ci = 0; ci < NC; ci++) {
        CP_WAIT0();
        __syncthreads();
        if (ci + 1 < NC) issue(ci + 1);
        uint32_t st = sbase + (uint32_t)(ci & 1) * STAGE_BYTES;
#pragma unroll
        for (int ks = 0; ks < 2; ks++) {
            uint32_t koff = ks * 32;
            uint32_t ah[4][4], al[4][4];
#pragma unroll
            for (int mi = 0; mi < 4; mi++) {
                ldsm4(ah[mi], st + (swA[mi] ^ koff));
                ldsm4(al[mi], st + (swA[mi] ^ (koff + 64)));
            }
#pragma unroll
            for (int g = 0; g < 2; g++) {
                uint32_t bh[4];
                ldsm4(bh, st + (swB[g] ^ koff));
#pragma unroll
                for (int mi = 0; mi < 4; mi++) {
                    mma16816h(acc[mi][2 * g + 0], ah[mi], bh[0], bh[2]);
                    mma16816h(acc[mi][2 * g + 1], ah[mi], bh[1], bh[3]);
                    mma16816h(acc[mi][2 * g + 0], al[mi], bh[0], bh[2]);
                    mma16816h(acc[mi][2 * g + 1], al[mi], bh[1], bh[3]);
                }
            }
        }
    }

    // epilogue
    int rw0 = rowBase + warpM * 64 + (lane >> 2);
    int cw0 = colBase + warpN * 32 + (lane & 3) * 2;
#pragma unroll
    for (int mi = 0; mi < 4; mi++) {
#pragma unroll
        for (int nj = 0; nj < 4; nj++) {
            int col = cw0 + nj * 8;
            float b0 = bias[col], b1 = bias[col + 1];
            if (bias2) { b0 += bias2[col]; b1 += bias2[col + 1]; }
#pragma unroll
            for (int h = 0; h < 2; h++) {
                int row_ = rw0 + mi * 16 + h * 8;
                if (row_ < M) {
                    float v0 = acc[mi][nj][2 * h + 0] + b0;
                    float v1 = acc[mi][nj][2 * h + 1] + b1;
                    long off = (long)row_ * ldc + colOff + col;
                    if (GELU) {
                        float g0 = 0.5f * v0 * (1.0f + erff(v0 * 0.70710678118654752f));
                        float g1 = 0.5f * v1 * (1.0f + erff(v1 * 0.70710678118654752f));
                        float h0 = __half2float(__float2half_rn(g0));
                        float h1 = __half2float(__float2half_rn(g1));
                        *(uint32_t*)(Chi + off) = pack_h2(g0, g1);
                        *(uint32_t*)(Clo + off) = pack_h2(g0 - h0, g1 - h1);
                    } else {
                        float2 v; v.x = v0; v.y = v1;
                        *(float2*)(Cf + off) = v;
                    }
                }
            }
        }
    }
}

// GEMM1: z<8 routed expert z (gather); z>=8 shared n=z-8.
__global__ __launch_bounds__(128, 4)
void moe_gemm1(const __half* __restrict__ x_hi,
               const __half* __restrict__ x_lo,
               const float* __restrict__ sb1, const float* __restrict__ eb1,
               int zBase)
{
    int z = blockIdx.z + zBase;
    int M, ldc, colOff;
    const int* list;
    const __half* Bh;
    const float* bias;
    __half *Ch, *Cl;
    if (z < E_NUM) {
        M = g_counts[z];
        list = g_list + (long)z * T_TOK;
        Bh = g_ew1t + (size_t)z * F_DIM * H_DIM;
        bias = eb1 + z * F_DIM;
        long b = g_base[z];
        Ch = g_hidr_hi + b * (long)F_DIM;
        Cl = g_hidr_lo + b * (long)F_DIM;
        ldc = F_DIM; colOff = 0;
    } else {
        int n = z - E_NUM;
        M = T_TOK;
        list = nullptr;
        Bh = g_sw1t + (size_t)n * F_DIM * H_DIM;
        bias = sb1 + n * F_DIM;
        Ch = g_hids_hi; Cl = g_hids_lo;
        ldc = F2; colOff = n * F_DIM;
    }
    int rowBase = blockIdx.x * 128;
    if (rowBase >= M) return;
    gemm_core<true>(x_hi, x_lo, Bh, bias, nullptr,
                    Ch, Cl, nullptr, M, H_DIM, ldc, colOff, list, rowBase);
}

// GEMM2: z<8 routed (K=F); z==8 shared (K=F2, writes out).
__global__ __launch_bounds__(128, 4)
void moe_gemm2(const float* __restrict__ sb2, const float* __restrict__ eb2,
               float* __restrict__ out)
{
    int z = blockIdx.z;
    int M, K;
    const __half *Ah, *Al, *Bh;
    const float *bias, *bias2;
    float* Cf;
    if (z < E_NUM) {
        M = g_counts[z];
        long b = g_base[z];
        Ah = g_hidr_hi + b * (long)F_DIM;
        Al = g_hidr_lo + b * (long)F_DIM;
        K = F_DIM;
        Bh = g_ew2t + (size_t)z * H_DIM * F_DIM;
        bias = eb2 + z * H_DIM; bias2 = nullptr;
        Cf = g_rout + b * (long)H_DIM;
    } else {
        M = T_TOK;
        Ah = g_hids_hi; Al = g_hids_lo;
        K = F2;
        Bh = g_sw2t;
        bias = sb2; bias2 = sb2 + H_DIM;
        Cf = out;
    }
    int rowBase = blockIdx.x * 128;
    if (rowBase >= M) return;
    gemm_core<false>(Ah, Al, Bh, bias, bias2,
                     nullptr, nullptr, Cf, M, K, H_DIM, 0, nullptr, rowBase);
}

// ===================== launch =====================
static void* symAddr(const void* sym) { void* p; cudaGetSymbolAddress(&p, sym); return p; }

extern "C" void kernel_launch(void* const* d_in, const int* in_sizes, int n_in,
                              void* d_out, int out_size)
{
    const float* x   = (const float*)d_in[0];
    const float* sw1 = (const float*)d_in[1];
    const float* sb1 = (const float*)d_in[2];
    const float* sw2 = (const float*)d_in[3];
    const float* sb2 = (const float*)d_in[4];
    const float* ew1 = (const float*)d_in[5];
    const float* eb1 = (const float*)d_in[6];
    const float* ew2 = (const float*)d_in[7];
    const float* eb2 = (const float*)d_in[8];
    const float* rw  = (const float*)d_in[9];
    const float* rb  = (const float*)d_in[10];
    float* out = (float*)d_out;

    __half* x_hi = (__half*)symAddr(g_x_hi);
    __half* x_lo = (__half*)symAddr(g_x_lo);

    cudaFuncSetAttribute(moe_gemm1, cudaFuncAttributeMaxDynamicSharedMemorySize, DSMEM_BYTES);
    cudaFuncSetAttribute(moe_gemm2, cudaFuncAttributeMaxDynamicSharedMemorySize, DSMEM_BYTES);

    // 1
    split_kernel<<<(T_TOK * H_DIM / 4 + 255) / 256, 256>>>(x, x_hi, x_lo, T_TOK * H_DIM / 4);
    // 2
    tsplitG1<<<dim3(F_DIM / 32, H_DIM / 32, E_NUM + 2), dim3(32, 8)>>>(sw1, ew1);
    // 3
    zero_kernel<<<1, 32>>>();
    // 4 (PROFILED): shared GEMM1
    moe_gemm1<<<dim3(T_TOK / 128, F_DIM / 64, 2), 128, DSMEM_BYTES>>>(
        x_hi, x_lo, sb1, eb1, E_NUM);
    // 5
    router_kernel<<<T_TOK / 4, 128>>>(x, rw, rb);
    // 6
    base_kernel<<<1, 32>>>();
    // 7: routed GEMM1
    moe_gemm1<<<dim3(T_TOK / 128, F_DIM / 64, E_NUM), 128, DSMEM_BYTES>>>(
        x_hi, x_lo, sb1, eb1, 0);
    // 8
    tsplitG2<<<dim3(H_DIM / 32, F_DIM / 32, E_NUM + 2), dim3(32, 8)>>>(sw2, ew2);
    // 9
    moe_gemm2<<<dim3(T_TOK / 128, H_DIM / 64, E_NUM + 1), 128, DSMEM_BYTES>>>(
        sb2, eb2, out);
    // 10
    combine_kernel<<<T_TOK, 256>>>(out);
}

// round 11
// speedup vs baseline: 1.5757x; 1.0234x over previous
#include <cuda_runtime.h>
#include <cuda_fp16.h>
#include <cstdint>
#include <math.h>

#define T_TOK 4096
#define H_DIM 1024
#define F_DIM 2048
#define E_NUM 8
#define F2    (2 * F_DIM)

// ===================== helpers =====================
__device__ __forceinline__ uint32_t smem_u32(const void* p) {
    uint32_t a;
    asm("{ .reg .u64 t; cvta.to.shared.u64 t, %1; cvt.u32.u64 %0, t; }" : "=r"(a) : "l"(p));
    return a;
}
#define SW128(off) ((off) ^ (((off) >> 3) & 0x70))

__device__ __forceinline__ void cp_async16(uint32_t dst, const void* src, int srcBytes) {
    asm volatile("cp.async.cg.shared.global [%0], [%1], 16, %2;"
                 :: "r"(dst), "l"(src), "r"(srcBytes) : "memory");
}
#define CP_COMMIT() asm volatile("cp.async.commit_group;" ::: "memory")
#define CP_WAIT(n)  asm volatile("cp.async.wait_group %0;" :: "n"(n) : "memory")

__device__ __forceinline__ void ldsm4(uint32_t* r, uint32_t addr) {
    asm volatile("ldmatrix.sync.aligned.m8n8.x4.shared.b16 {%0,%1,%2,%3}, [%4];"
                 : "=r"(r[0]), "=r"(r[1]), "=r"(r[2]), "=r"(r[3]) : "r"(addr));
}

__device__ __forceinline__ void mma16816h(float* d, const uint32_t* a, uint32_t b0, uint32_t b1) {
    asm volatile("mma.sync.aligned.m16n8k16.row.col.f32.f16.f16.f32 "
                 "{%0,%1,%2,%3}, {%4,%5,%6,%7}, {%8,%9}, {%0,%1,%2,%3};"
                 : "+f"(d[0]), "+f"(d[1]), "+f"(d[2]), "+f"(d[3])
                 : "r"(a[0]), "r"(a[1]), "r"(a[2]), "r"(a[3]), "r"(b0), "r"(b1));
}

__device__ __forceinline__ uint32_t pack_h2(float x, float y) {
    __half2 t = __floats2half2_rn(x, y);
    return *(uint32_t*)&t;
}

// ===================== scratch =====================
__device__ __half g_x_hi [(size_t)T_TOK * H_DIM];
__device__ __half g_x_lo [(size_t)T_TOK * H_DIM];
__device__ __half g_sw1t [(size_t)2 * F_DIM * H_DIM];
__device__ __half g_ew1t [(size_t)E_NUM * F_DIM * H_DIM];
__device__ __half g_sw2t [(size_t)H_DIM * F2];
__device__ __half g_ew2t [(size_t)E_NUM * H_DIM * F_DIM];
__device__ __half g_hids_hi[(size_t)T_TOK * F2];
__device__ __half g_hids_lo[(size_t)T_TOK * F2];
__device__ __half g_hidr_hi[(size_t)2 * T_TOK * F_DIM];
__device__ __half g_hidr_lo[(size_t)2 * T_TOK * F_DIM];
__device__ float g_rout[(size_t)2 * T_TOK * H_DIM];
__device__ int g_counts[E_NUM];
__device__ int g_base[E_NUM];
__device__ int g_list[E_NUM * T_TOK];
__device__ int g_tok_e[2 * T_TOK];
__device__ int g_tok_slot[2 * T_TOK];

// ===================== small kernels =====================
__global__ void zero_kernel() {
    if (threadIdx.x < E_NUM) g_counts[threadIdx.x] = 0;
}

__global__ void router_kernel(const float* __restrict__ x,
                              const float* __restrict__ rw,
                              const float* __restrict__ rb) {
    int warp = (blockIdx.x * blockDim.x + threadIdx.x) >> 5;
    int lane = threadIdx.x & 31;
    if (warp >= T_TOK) return;
    const float* xp = x + (long)warp * H_DIM;
    float acc[E_NUM];
#pragma unroll
    for (int e = 0; e < E_NUM; e++) acc[e] = 0.f;
    for (int h = lane; h < H_DIM; h += 32) {
        float xv = xp[h];
        const float* w = rw + (long)h * E_NUM;
#pragma unroll
        for (int e = 0; e < E_NUM; e++) acc[e] = fmaf(xv, w[e], acc[e]);
    }
#pragma unroll
    for (int e = 0; e < E_NUM; e++)
#pragma unroll
        for (int off = 16; off; off >>= 1)
            acc[e] += __shfl_xor_sync(0xFFFFFFFFu, acc[e], off);
    if (lane == 0) {
        float lg[E_NUM];
#pragma unroll
        for (int e = 0; e < E_NUM; e++) lg[e] = acc[e] + rb[e];
        int e0 = 0;
#pragma unroll
        for (int e = 1; e < E_NUM; e++) if (lg[e] > lg[e0]) e0 = e;
        int e1 = -1;
#pragma unroll
        for (int e = 0; e < E_NUM; e++) {
            if (e == e0) continue;
            if (e1 < 0 || lg[e] > lg[e1]) e1 = e;
        }
        int sel[2] = { e0, e1 };
        int t = warp;
#pragma unroll
        for (int k = 0; k < 2; k++) {
            int e = sel[k];
            int slot = atomicAdd(&g_counts[e], 1);
            g_list[e * T_TOK + slot] = t;
            g_tok_e[2 * t + k] = e;
            g_tok_slot[2 * t + k] = slot;
        }
    }
}

__global__ void base_kernel() {
    if (threadIdx.x == 0) {
        int s = 0;
#pragma unroll
        for (int e = 0; e < E_NUM; e++) { g_base[e] = s; s += g_counts[e]; }
    }
}

__global__ void combine_kernel(float* __restrict__ out) {
    int t = blockIdx.x;
    int e0 = g_tok_e[2 * t], e1 = g_tok_e[2 * t + 1];
    long r0 = (long)g_base[e0] + g_tok_slot[2 * t];
    long r1 = (long)g_base[e1] + g_tok_slot[2 * t + 1];
    const float4* p0 = (const float4*)g_rout + r0 * (H_DIM / 4);
    const float4* p1 = (const float4*)g_rout + r1 * (H_DIM / 4);
    float4* op = (float4*)out + (long)t * (H_DIM / 4);
    int i = threadIdx.x;
    float4 o = op[i], a = p0[i], b = p1[i];
    o.x += a.x + b.x; o.y += a.y + b.y; o.z += a.z + b.z; o.w += a.w + b.w;
    op[i] = o;
}

// ===================== converters =====================
__global__ void split_kernel(const float* __restrict__ in,
                             __half* __restrict__ hi,
                             __half* __restrict__ lo, int n4) {
    int i = blockIdx.x * blockDim.x + threadIdx.x;
    if (i >= n4) return;
    float4 v = ((const float4*)in)[i];
    union { __half b[4]; uint2 u; } hb, lb;
    float vv[4] = { v.x, v.y, v.z, v.w };
#pragma unroll
    for (int u = 0; u < 4; u++) {
        __half h = __float2half_rn(vv[u]);
        hb.b[u] = h;
        lb.b[u] = __float2half_rn(vv[u] - __half2float(h));
    }
    ((uint2*)hi)[i] = hb.u;
    ((uint2*)lo)[i] = lb.u;
}

__global__ void tsplitG1(const float* __restrict__ sw1, const float* __restrict__ ew1) {
    __shared__ float t[32][33];
    int z = blockIdx.z;
    const float* src;
    __half* hi;
    if (z < E_NUM) {
        src = ew1 + (size_t)z * H_DIM * F_DIM;
        hi = g_ew1t + (size_t)z * F_DIM * H_DIM;
    } else {
        int n = z - E_NUM;
        src = sw1 + (size_t)n * H_DIM * F_DIM;
        hi = g_sw1t + (size_t)n * F_DIM * H_DIM;
    }
    int n0 = blockIdx.x * 32, k0 = blockIdx.y * 32;
    int tx = threadIdx.x, ty = threadIdx.y;
#pragma unroll
    for (int i = 0; i < 32; i += 8)
        t[ty + i][tx] = src[(long)(k0 + ty + i) * F_DIM + n0 + tx];
    __syncthreads();
#pragma unroll
    for (int i = 0; i < 32; i += 8)
        hi[(long)(n0 + ty + i) * H_DIM + k0 + tx] = __float2half_rn(t[tx][ty + i]);
}

__global__ void tsplitG2(const float* __restrict__ sw2, const float* __restrict__ ew2) {
    __shared__ float t[32][33];
    int z = blockIdx.z;
    const float* src;
    __half* hi;
    long obase; int ld;
    if (z < E_NUM) {
        src = ew2 + (size_t)z * F_DIM * H_DIM;
        hi = g_ew2t;
        obase = (size_t)z * H_DIM * F_DIM; ld = F_DIM;
    } else {
        int n = z - E_NUM;
        src = sw2 + (size_t)n * F_DIM * H_DIM;
        hi = g_sw2t;
        obase = (long)n * F_DIM; ld = F2;
    }
    int n0 = blockIdx.x * 32, k0 = blockIdx.y * 32;
    int tx = threadIdx.x, ty = threadIdx.y;
#pragma unroll
    for (int i = 0; i < 32; i += 8)
        t[ty + i][tx] = src[(long)(k0 + ty + i) * H_DIM + n0 + tx];
    __syncthreads();
#pragma unroll
    for (int i = 0; i < 32; i += 8)
        hi[obase + (long)(n0 + ty + i) * ld + k0 + tx] = __float2half_rn(t[tx][ty + i]);
}

// ===================== GEMM core: CTA 128x128, 256 thr, warp 32x64 ==========
// fp16 2-product: C = (Ah + Al) @ Bh^T.
// A stage: 128 rows x 128B = [Ah k0..31 | Al k0..31] -> 16KB.
// B stage: 64 rows x 128B; row p = [Bh[n=p] k0..31 | Bh[n=p+64] k0..31] -> 8KB.
// 3 stages, prefetch depth 2, ONE __syncthreads per BK=32 chunk.
#define STAGE_BYTES 24576
#define B_OFF 16384
#define DSMEM_BYTES (3 * STAGE_BYTES)

template<bool GELU>
__device__ __forceinline__ void gemm_core(
    const __half* __restrict__ Ahi, const __half* __restrict__ Alo,
    const __half* __restrict__ Bh,
    const float* __restrict__ bias, const float* __restrict__ bias2,
    __half* Chi, __half* Clo, float* Cf,
    int M, int K, int ldc, int colOff, const int* list, int rowBase)
{
    int colBase = blockIdx.y * 128;
    extern __shared__ char smem[];
    uint32_t sbase = smem_u32(smem);
    int tid = threadIdx.x;
    int wid = tid >> 5, lane = tid & 31;
    int warpM = wid & 3, warpN = wid >> 2;   // 4m x 2n, warp tile 32x64

    // ---- loader metadata ----
    int c = tid & 7;                 // 16B chunk within 128B row
    bool hiSel = c < 4;
    int kel = (c & 3) * 8;           // fp16 elem offset within 32-wide K chunk
    int rA = tid >> 3;               // 0..31 (A rows, 4 units of 32)
    uint32_t swA0 = SW128((uint32_t)(rA * 128 + c * 16));
    const __half* ApA = hiSel ? Ahi : Alo;
    int aRow[4]; uint32_t aOk = 0;
#pragma unroll
    for (int i = 0; i < 4; i++) {
        int gR = rowBase + rA + 32 * i;
        bool ok = gR < M;
        if (ok) aOk |= (1u << i);
        aRow[i] = list ? (ok ? list[gR] : 0) : (ok ? gR : 0);
    }
    // B: 512 units / 256 thr = 2 units; unit u = tid + 256*j -> row p = u>>3 (0..63)
    // n = p + 64*(c>=4)
    int bN0 = colBase + rA + (hiSel ? 0 : 64);   // j=0: p = rA
    int bN1 = colBase + rA + 32 + (hiSel ? 0 : 64); // j=1: p = rA+32
    uint32_t swB0 = B_OFF + swA0;                 // p=rA, same in-row chunk c
    uint32_t swB1 = B_OFF + SW128((uint32_t)((rA + 32) * 128 + c * 16));

    const int NC = K >> 5;
    auto issue = [&](int ci) {
        uint32_t st = sbase + (uint32_t)(ci % 3) * STAGE_BYTES;
        int kbase = ci << 5;
#pragma unroll
        for (int i = 0; i < 4; i++)
            cp_async16(st + swA0 + 4096u * i,
                       ApA + (long)aRow[i] * K + kbase + kel,
                       (aOk >> i) & 1 ? 16 : 0);
        cp_async16(st + swB0, Bh + (long)bN0 * K + kbase + kel, 16);
        cp_async16(st + swB1, Bh + (long)bN1 * K + kbase + kel, 16);
        CP_COMMIT();
    };

    float acc[2][8][4];
#pragma unroll
    for (int mi = 0; mi < 2; mi++)
#pragma unroll
        for (int nj = 0; nj < 8; nj++)
#pragma unroll
            for (int u = 0; u < 4; u++) acc[mi][nj][u] = 0.f;

    int lrow = lane & 15;
    int lc16 = (lane >> 4) * 16;
    uint32_t swA[2], swB[4];
#pragma unroll
    for (int mi = 0; mi < 2; mi++)
        swA[mi] = SW128((uint32_t)((warpM * 32 + mi * 16 + lrow) * 128 + lc16));
#pragma unroll
    for (int g = 0; g < 4; g++)   // n-local rows p = g*16+lrow; col half = warpN
        swB[g] = B_OFF + SW128((uint32_t)((g * 16 + lrow) * 128 + warpN * 64 + lc16));

    issue(0); issue(1);
    for (int ci = 0; ci < NC; ci++) {
        CP_WAIT(1);
        __syncthreads();
        if (ci + 2 < NC) issue(ci + 2);
        else CP_COMMIT();
        uint32_t st = sbase + (uint32_t)(ci % 3) * STAGE_BYTES;
#pragma unroll
        for (int ks = 0; ks < 2; ks++) {
            uint32_t koff = ks * 32;
            uint32_t ah[2][4], al[2][4];
#pragma unroll
            for (int mi = 0; mi < 2; mi++) {
                ldsm4(ah[mi], st + (swA[mi] ^ koff));
                ldsm4(al[mi], st + (swA[mi] ^ (koff + 64)));
            }
#pragma unroll
            for (int g = 0; g < 4; g++) {
                uint32_t bh[4];
                ldsm4(bh, st + (swB[g] ^ koff));
#pragma unroll
                for (int mi = 0; mi < 2; mi++) {
                    mma16816h(acc[mi][2 * g + 0], ah[mi], bh[0], bh[2]);
                    mma16816h(acc[mi][2 * g + 1], ah[mi], bh[1], bh[3]);
                    mma16816h(acc[mi][2 * g + 0], al[mi], bh[0], bh[2]);
                    mma16816h(acc[mi][2 * g + 1], al[mi], bh[1], bh[3]);
                }
            }
        }
    }

    // epilogue
    int rw0 = rowBase + warpM * 32 + (lane >> 2);
    int cw0 = colBase + warpN * 64 + (lane & 3) * 2;
#pragma unroll
    for (int mi = 0; mi < 2; mi++) {
#pragma unroll
        for (int nj = 0; nj < 8; nj++) {
            int col = cw0 + nj * 8;
            float b0 = bias[col], b1 = bias[col + 1];
            if (bias2) { b0 += bias2[col]; b1 += bias2[col + 1]; }
#pragma unroll
            for (int h = 0; h < 2; h++) {
                int row_ = rw0 + mi * 16 + h * 8;
                if (row_ < M) {
                    float v0 = acc[mi][nj][2 * h + 0] + b0;
                    float v1 = acc[mi][nj][2 * h + 1] + b1;
                    long off = (long)row_ * ldc + colOff + col;
                    if (GELU) {
                        float g0 = 0.5f * v0 * (1.0f + erff(v0 * 0.70710678118654752f));
                        float g1 = 0.5f * v1 * (1.0f + erff(v1 * 0.70710678118654752f));
                        float h0 = __half2float(__float2half_rn(g0));
                        float h1 = __half2float(__float2half_rn(g1));
                        *(uint32_t*)(Chi + off) = pack_h2(g0, g1);
                        *(uint32_t*)(Clo + off) = pack_h2(g0 - h0, g1 - h1);
                    } else {
                        float2 v; v.x = v0; v.y = v1;
                        *(float2*)(Cf + off) = v;
                    }
                }
            }
        }
    }
}

// GEMM1: z<8 routed expert z (gather); z>=8 shared n=z-8.
__global__ __launch_bounds__(256, 2)
void moe_gemm1(const __half* __restrict__ x_hi,
               const __half* __restrict__ x_lo,
               const float* __restrict__ sb1, const float* __restrict__ eb1,
               int zBase)
{
    int z = blockIdx.z + zBase;
    int M, ldc, colOff;
    const int* list;
    const __half* Bh;
    const float* bias;
    __half *Ch, *Cl;
    if (z < E_NUM) {
        M = g_counts[z];
        list = g_list + (long)z * T_TOK;
        Bh = g_ew1t + (size_t)z * F_DIM * H_DIM;
        bias = eb1 + z * F_DIM;
        long b = g_base[z];
        Ch = g_hidr_hi + b * (long)F_DIM;
        Cl = g_hidr_lo + b * (long)F_DIM;
        ldc = F_DIM; colOff = 0;
    } else {
        int n = z - E_NUM;
        M = T_TOK;
        list = nullptr;
        Bh = g_sw1t + (size_t)n * F_DIM * H_DIM;
        bias = sb1 + n * F_DIM;
        Ch = g_hids_hi; Cl = g_hids_lo;
        ldc = F2; colOff = n * F_DIM;
    }
    int rowBase = blockIdx.x * 128;
    if (rowBase >= M) return;
    gemm_core<true>(x_hi, x_lo, Bh, bias, nullptr,
                    Ch, Cl, nullptr, M, H_DIM, ldc, colOff, list, rowBase);
}

// GEMM2: z<8 routed (K=F); z==8 shared (K=F2, writes out).
__global__ __launch_bounds__(256, 2)
void moe_gemm2(const float* __restrict__ sb2, const float* __restrict__ eb2,
               float* __restrict__ out)
{
    int z = blockIdx.z;
    int M, K;
    const __half *Ah, *Al, *Bh;
    const float *bias, *bias2;
    float* Cf;
    if (z < E_NUM) {
        M = g_counts[z];
        long b = g_base[z];
        Ah = g_hidr_hi + b * (long)F_DIM;
        Al = g_hidr_lo + b * (long)F_DIM;
        K = F_DIM;
        Bh = g_ew2t + (size_t)z * H_DIM * F_DIM;
        bias = eb2 + z * H_DIM; bias2 = nullptr;
        Cf = g_rout + b * (long)H_DIM;
    } else {
        M = T_TOK;
        Ah = g_hids_hi; Al = g_hids_lo;
        K = F2;
        Bh = g_sw2t;
        bias = sb2; bias2 = sb2 + H_DIM;
        Cf = out;
    }
    int rowBase = blockIdx.x * 128;
    if (rowBase >= M) return;
    gemm_core<false>(Ah, Al, Bh, bias, bias2,
                     nullptr, nullptr, Cf, M, K, H_DIM, 0, nullptr, rowBase);
}

// ===================== launch =====================
static void* symAddr(const void* sym) { void* p; cudaGetSymbolAddress(&p, sym); return p; }

extern "C" void kernel_launch(void* const* d_in, const int* in_sizes, int n_in,
                              void* d_out, int out_size)
{
    const float* x   = (const float*)d_in[0];
    const float* sw1 = (const float*)d_in[1];
    const float* sb1 = (const float*)d_in[2];
    const float* sw2 = (const float*)d_in[3];
    const float* sb2 = (const float*)d_in[4];
    const float* ew1 = (const float*)d_in[5];
    const float* eb1 = (const float*)d_in[6];
    const float* ew2 = (const float*)d_in[7];
    const float* eb2 = (const float*)d_in[8];
    const float* rw  = (const float*)d_in[9];
    const float* rb  = (const float*)d_in[10];
    float* out = (float*)d_out;

    __half* x_hi = (__half*)symAddr(g_x_hi);
    __half* x_lo = (__half*)symAddr(g_x_lo);

    cudaFuncSetAttribute(moe_gemm1, cudaFuncAttributeMaxDynamicSharedMemorySize, DSMEM_BYTES);
    cudaFuncSetAttribute(moe_gemm2, cudaFuncAttributeMaxDynamicSharedMemorySize, DSMEM_BYTES);

    // 1
    split_kernel<<<(T_TOK * H_DIM / 4 + 255) / 256, 256>>>(x, x_hi, x_lo, T_TOK * H_DIM / 4);
    // 2
    tsplitG1<<<dim3(F_DIM / 32, H_DIM / 32, E_NUM + 2), dim3(32, 8)>>>(sw1, ew1);
    // 3
    zero_kernel<<<1, 32>>>();
    // 4 (PROFILED): shared GEMM1
    moe_gemm1<<<dim3(T_TOK / 128, F_DIM / 128, 2), 256, DSMEM_BYTES>>>(
        x_hi, x_lo, sb1, eb1, E_NUM);
    // 5
    router_kernel<<<T_TOK / 4, 128>>>(x, rw, rb);
    // 6
    base_kernel<<<1, 32>>>();
    // 7: routed GEMM1
    moe_gemm1<<<dim3(T_TOK / 128, F_DIM / 128, E_NUM), 256, DSMEM_BYTES>>>(
        x_hi, x_lo, sb1, eb1, 0);
    // 8
    tsplitG2<<<dim3(H_DIM / 32, F_DIM / 32, E_NUM + 2), dim3(32, 8)>>>(sw2, ew2);
    // 9
    moe_gemm2<<<dim3(T_TOK / 128, H_DIM / 128, E_NUM + 1), 256, DSMEM_BYTES>>>(
        sb2, eb2, out);
    // 10
    combine_kernel<<<T_TOK, 256>>>(out);
}

// round 12
// speedup vs baseline: 3.1066x; 1.9716x over previous
#include <cuda_runtime.h>
#include <cuda_fp16.h>
#include <cstdint>
#include <math.h>

#define T_TOK 4096
#define H_DIM 1024
#define F_DIM 2048
#define E_NUM 8
#define F2    (2 * F_DIM)

// ===================== helpers =====================
__device__ __forceinline__ uint32_t smem_u32(const void* p) {
    uint32_t a;
    asm("{ .reg .u64 t; cvta.to.shared.u64 t, %1; cvt.u32.u64 %0, t; }" : "=r"(a) : "l"(p));
    return a;
}
#define SW128(off) ((off) ^ (((off) >> 3) & 0x70))

__device__ __forceinline__ void cp_async16(uint32_t dst, const void* src, int srcBytes) {
    asm volatile("cp.async.cg.shared.global [%0], [%1], 16, %2;"
                 :: "r"(dst), "l"(src), "r"(srcBytes) : "memory");
}
#define CP_COMMIT() asm volatile("cp.async.commit_group;" ::: "memory")
#define CP_WAIT(n)  asm volatile("cp.async.wait_group %0;" :: "n"(n) : "memory")

__device__ __forceinline__ void ldsm4(uint32_t* r, uint32_t addr) {
    asm volatile("ldmatrix.sync.aligned.m8n8.x4.shared.b16 {%0,%1,%2,%3}, [%4];"
                 : "=r"(r[0]), "=r"(r[1]), "=r"(r[2]), "=r"(r[3]) : "r"(addr));
}

__device__ __forceinline__ void mma16816h(float* d, const uint32_t* a, uint32_t b0, uint32_t b1) {
    asm volatile("mma.sync.aligned.m16n8k16.row.col.f32.f16.f16.f32 "
                 "{%0,%1,%2,%3}, {%4,%5,%6,%7}, {%8,%9}, {%0,%1,%2,%3};"
                 : "+f"(d[0]), "+f"(d[1]), "+f"(d[2]), "+f"(d[3])
                 : "r"(a[0]), "r"(a[1]), "r"(a[2]), "r"(a[3]), "r"(b0), "r"(b1));
}

__device__ __forceinline__ uint32_t pack_h2(float x, float y) {
    __half2 t = __floats2half2_rn(x, y);
    return *(uint32_t*)&t;
}

// ===================== scratch =====================
__device__ __half g_x_h  [(size_t)T_TOK * H_DIM];
__device__ __half g_sw1t [(size_t)2 * F_DIM * H_DIM];
__device__ __half g_ew1t [(size_t)E_NUM * F_DIM * H_DIM];
__device__ __half g_sw2t [(size_t)2 * H_DIM * F_DIM];
__device__ __half g_ew2t [(size_t)E_NUM * H_DIM * F_DIM];
__device__ __half g_hids [(size_t)T_TOK * F2];
__device__ __half g_hidr [(size_t)2 * T_TOK * F_DIM];
__device__ float g_rout [(size_t)2 * T_TOK * H_DIM];
__device__ float g_part0[(size_t)T_TOK * H_DIM];
__device__ float g_part1[(size_t)T_TOK * H_DIM];
__device__ float g_zb[H_DIM];          // zero bias (static zero-init)
__device__ int g_counts[E_NUM];
__device__ int g_base[E_NUM];
__device__ int g_list[E_NUM * T_TOK];
__device__ int g_tok_e[2 * T_TOK];
__device__ int g_tok_slot[2 * T_TOK];

// ===================== small kernels =====================
__global__ void zero_kernel() {
    if (threadIdx.x < E_NUM) g_counts[threadIdx.x] = 0;
}

__global__ void router_kernel(const float* __restrict__ x,
                              const float* __restrict__ rw,
                              const float* __restrict__ rb) {
    int warp = (blockIdx.x * blockDim.x + threadIdx.x) >> 5;
    int lane = threadIdx.x & 31;
    if (warp >= T_TOK) return;
    const float* xp = x + (long)warp * H_DIM;
    float acc[E_NUM];
#pragma unroll
    for (int e = 0; e < E_NUM; e++) acc[e] = 0.f;
    for (int h = lane; h < H_DIM; h += 32) {
        float xv = xp[h];
        const float* w = rw + (long)h * E_NUM;
#pragma unroll
        for (int e = 0; e < E_NUM; e++) acc[e] = fmaf(xv, w[e], acc[e]);
    }
#pragma unroll
    for (int e = 0; e < E_NUM; e++)
#pragma unroll
        for (int off = 16; off; off >>= 1)
            acc[e] += __shfl_xor_sync(0xFFFFFFFFu, acc[e], off);
    if (lane == 0) {
        float lg[E_NUM];
#pragma unroll
        for (int e = 0; e < E_NUM; e++) lg[e] = acc[e] + rb[e];
        int e0 = 0;
#pragma unroll
        for (int e = 1; e < E_NUM; e++) if (lg[e] > lg[e0]) e0 = e;
        int e1 = -1;
#pragma unroll
        for (int e = 0; e < E_NUM; e++) {
            if (e == e0) continue;
            if (e1 < 0 || lg[e] > lg[e1]) e1 = e;
        }
        int sel[2] = { e0, e1 };
        int t = warp;
#pragma unroll
        for (int k = 0; k < 2; k++) {
            int e = sel[k];
            int slot = atomicAdd(&g_counts[e], 1);
            g_list[e * T_TOK + slot] = t;
            g_tok_e[2 * t + k] = e;
            g_tok_slot[2 * t + k] = slot;
        }
    }
}

__global__ void base_kernel() {
    if (threadIdx.x == 0) {
        int s = 0;
#pragma unroll
        for (int e = 0; e < E_NUM; e++) { g_base[e] = s; s += g_counts[e]; }
    }
}

// out = part0 + part1 + routed0 + routed1
__global__ void combine_kernel(float* __restrict__ out) {
    int t = blockIdx.x;
    int e0 = g_tok_e[2 * t], e1 = g_tok_e[2 * t + 1];
    long r0 = (long)g_base[e0] + g_tok_slot[2 * t];
    long r1 = (long)g_base[e1] + g_tok_slot[2 * t + 1];
    int i = threadIdx.x;                      // 256 = H/4
    long ti = (long)t * (H_DIM / 4) + i;
    const float4 a = ((const float4*)g_part0)[ti];
    const float4 b = ((const float4*)g_part1)[ti];
    const float4 c = ((const float4*)g_rout)[r0 * (H_DIM / 4) + i];
    const float4 d = ((const float4*)g_rout)[r1 * (H_DIM / 4) + i];
    float4 o;
    o.x = a.x + b.x + c.x + d.x;
    o.y = a.y + b.y + c.y + d.y;
    o.z = a.z + b.z + c.z + d.z;
    o.w = a.w + b.w + c.w + d.w;
    ((float4*)out)[ti] = o;
}

// ===================== converters =====================
__global__ void split_kernel(const float* __restrict__ in,
                             __half* __restrict__ hi, int n4) {
    int i = blockIdx.x * blockDim.x + threadIdx.x;
    if (i >= n4) return;
    float4 v = ((const float4*)in)[i];
    union { __half b[4]; uint2 u; } hb;
    hb.b[0] = __float2half_rn(v.x);
    hb.b[1] = __float2half_rn(v.y);
    hb.b[2] = __float2half_rn(v.z);
    hb.b[3] = __float2half_rn(v.w);
    ((uint2*)hi)[i] = hb.u;
}

// w1 [H][F] per slice -> K-major [F][H] half. z<8: ew1[z]; z>=8: sw1[z-8].
__global__ void tsplitG1(const float* __restrict__ sw1, const float* __restrict__ ew1) {
    __shared__ float t[32][33];
    int z = blockIdx.z;
    const float* src;
    __half* hi;
    if (z < E_NUM) {
        src = ew1 + (size_t)z * H_DIM * F_DIM;
        hi = g_ew1t + (size_t)z * F_DIM * H_DIM;
    } else {
        int n = z - E_NUM;
        src = sw1 + (size_t)n * H_DIM * F_DIM;
        hi = g_sw1t + (size_t)n * F_DIM * H_DIM;
    }
    int n0 = blockIdx.x * 32, k0 = blockIdx.y * 32;
    int tx = threadIdx.x, ty = threadIdx.y;
#pragma unroll
    for (int i = 0; i < 32; i += 8)
        t[ty + i][tx] = src[(long)(k0 + ty + i) * F_DIM + n0 + tx];
    __syncthreads();
#pragma unroll
    for (int i = 0; i < 32; i += 8)
        hi[(long)(n0 + ty + i) * H_DIM + k0 + tx] = __float2half_rn(t[tx][ty + i]);
}

// w2 [F][H] per slice -> K-major [H][F] half. z<8: ew2[z]; z>=8: sw2[z-8].
__global__ void tsplitG2(const float* __restrict__ sw2, const float* __restrict__ ew2) {
    __shared__ float t[32][33];
    int z = blockIdx.z;
    const float* src;
    __half* hi;
    if (z < E_NUM) {
        src = ew2 + (size_t)z * F_DIM * H_DIM;
        hi = g_ew2t + (size_t)z * H_DIM * F_DIM;
    } else {
        int n = z - E_NUM;
        src = sw2 + (size_t)n * F_DIM * H_DIM;
        hi = g_sw2t + (size_t)n * H_DIM * F_DIM;
    }
    int n0 = blockIdx.x * 32, k0 = blockIdx.y * 32;
    int tx = threadIdx.x, ty = threadIdx.y;
#pragma unroll
    for (int i = 0; i < 32; i += 8)
        t[ty + i][tx] = src[(long)(k0 + ty + i) * H_DIM + n0 + tx];
    __syncthreads();
#pragma unroll
    for (int i = 0; i < 32; i += 8)
        hi[(long)(n0 + ty + i) * F_DIM + k0 + tx] = __float2half_rn(t[tx][ty + i]);
}

// ===================== GEMM core: CTA 128x128, 256 thr, warp 32x64 ==========
// Plain fp16 single product: C = A @ B^T.  BK=64 (128B K-major rows).
// Stage = A 16KB + B 16KB = 32KB; 3 stages; prefetch depth 2; one sync/chunk.
#define STAGE_BYTES 32768
#define B_OFF 16384
#define DSMEM_BYTES (3 * STAGE_BYTES)

template<bool GELU>
__device__ __forceinline__ void gemm_core(
    const __half* __restrict__ Ah, const __half* __restrict__ Bh,
    const float* __restrict__ bias, const float* __restrict__ bias2,
    __half* Ch, float* Cf,
    int M, int K, int ldA, int ldc, int colOff, const int* list, int rowBase)
{
    int colBase = blockIdx.y * 128;
    extern __shared__ char smem[];
    uint32_t sbase = smem_u32(smem);
    int tid = threadIdx.x;
    int wid = tid >> 5, lane = tid & 31;
    int warpM = wid & 3, warpN = wid >> 2;   // 4m x 2n, warp tile 32x64

    // ---- loader metadata: 4 A units + 4 B units per thread ----
    int c = tid & 7;                 // 16B chunk within 128B row
    int kel = c * 8;                 // fp16 elem offset within 64-wide K chunk
    int r0 = tid >> 3;               // 0..31
    uint32_t swr = SW128((uint32_t)(r0 * 128 + c * 16));
    const __half* aSrc[4]; uint32_t aOk = 0;
#pragma unroll
    for (int i = 0; i < 4; i++) {
        int gR = rowBase + r0 + 32 * i;
        bool ok = gR < M;
        if (ok) aOk |= (1u << i);
        long rrow = list ? (ok ? list[gR] : 0) : (ok ? gR : 0);
        aSrc[i] = Ah + rrow * ldA + kel;
    }
    const __half* bSrc[4];
#pragma unroll
    for (int i = 0; i < 4; i++)
        bSrc[i] = Bh + (long)(colBase + r0 + 32 * i) * K + kel;

    const int NC = K >> 6;
    auto issue = [&](int ci) {
        uint32_t st = sbase + (uint32_t)(ci % 3) * STAGE_BYTES;
        int kbase = ci << 6;
#pragma unroll
        for (int i = 0; i < 4; i++)
            cp_async16(st + swr + 4096u * i, aSrc[i] + kbase,
                       (aOk >> i) & 1 ? 16 : 0);
#pragma unroll
        for (int i = 0; i < 4; i++)
            cp_async16(st + B_OFF + swr + 4096u * i, bSrc[i] + kbase, 16);
        CP_COMMIT();
    };

    float acc[2][8][4];
#pragma unroll
    for (int mi = 0; mi < 2; mi++)
#pragma unroll
        for (int nj = 0; nj < 8; nj++)
#pragma unroll
            for (int u = 0; u < 4; u++) acc[mi][nj][u] = 0.f;

    int lrow = lane & 15;
    int lc16 = (lane >> 4) * 16;
    uint32_t swA[2], swB[4];
#pragma unroll
    for (int mi = 0; mi < 2; mi++)
        swA[mi] = SW128((uint32_t)((warpM * 32 + mi * 16 + lrow) * 128 + lc16));
#pragma unroll
    for (int g = 0; g < 4; g++)
        swB[g] = B_OFF + SW128((uint32_t)((warpN * 64 + g * 16 + lrow) * 128 + lc16));

    issue(0); issue(1);
    for (int ci = 0; ci < NC; ci++) {
        CP_WAIT(1);
        __syncthreads();
        if (ci + 2 < NC) issue(ci + 2);
        else CP_COMMIT();
        uint32_t st = sbase + (uint32_t)(ci % 3) * STAGE_BYTES;
#pragma unroll
        for (int ks = 0; ks < 4; ks++) {
            uint32_t koff = ks * 32;
            uint32_t a[2][4];
#pragma unroll
            for (int mi = 0; mi < 2; mi++)
                ldsm4(a[mi], st + (swA[mi] ^ koff));
#pragma unroll
            for (int g = 0; g < 4; g++) {
                uint32_t b[4];
                ldsm4(b, st + (swB[g] ^ koff));
#pragma unroll
                for (int mi = 0; mi < 2; mi++) {
                    mma16816h(acc[mi][2 * g + 0], a[mi], b[0], b[2]);
                    mma16816h(acc[mi][2 * g + 1], a[mi], b[1], b[3]);
                }
            }
        }
    }

    // epilogue
    int rw0 = rowBase + warpM * 32 + (lane >> 2);
    int cw0 = colBase + warpN * 64 + (lane & 3) * 2;
#pragma unroll
    for (int mi = 0; mi < 2; mi++) {
#pragma unroll
        for (int nj = 0; nj < 8; nj++) {
            int col = cw0 + nj * 8;
            float b0 = bias[col], b1 = bias[col + 1];
            if (bias2) { b0 += bias2[col]; b1 += bias2[col + 1]; }
#pragma unroll
            for (int h = 0; h < 2; h++) {
                int row_ = rw0 + mi * 16 + h * 8;
                if (row_ < M) {
                    float v0 = acc[mi][nj][2 * h + 0] + b0;
                    float v1 = acc[mi][nj][2 * h + 1] + b1;
                    long off = (long)row_ * ldc + colOff + col;
                    if (GELU) {
                        float g0 = 0.5f * v0 * (1.0f + erff(v0 * 0.70710678118654752f));
                        float g1 = 0.5f * v1 * (1.0f + erff(v1 * 0.70710678118654752f));
                        *(uint32_t*)(Ch + off) = pack_h2(g0, g1);
                    } else {
                        float2 v; v.x = v0; v.y = v1;
                        *(float2*)(Cf + off) = v;
                    }
                }
            }
        }
    }
}

// GEMM1 merged: z<8 routed expert z (gather from x); z>=8 shared n=z-8.
__global__ __launch_bounds__(256, 2)
void moe_gemm1(const float* __restrict__ sb1, const float* __restrict__ eb1)
{
    int z = blockIdx.z;
    int M, ldc, colOff;
    const int* list;
    const __half* Bh;
    const float* bias;
    __half* Ch;
    if (z < E_NUM) {
        M = g_counts[z];
        list = g_list + (long)z * T_TOK;
        Bh = g_ew1t + (size_t)z * F_DIM * H_DIM;
        bias = eb1 + z * F_DIM;
        Ch = g_hidr + (long)g_base[z] * F_DIM;
        ldc = F_DIM; colOff = 0;
    } else {
        int n = z - E_NUM;
        M = T_TOK;
        list = nullptr;
        Bh = g_sw1t + (size_t)n * F_DIM * H_DIM;
        bias = sb1 + n * F_DIM;
        Ch = g_hids;
        ldc = F2; colOff = n * F_DIM;
    }
    int rowBase = blockIdx.x * 128;
    if (rowBase >= M) return;
    gemm_core<true>(g_x_h, Bh, bias, nullptr, Ch, nullptr,
                    M, H_DIM, H_DIM, ldc, colOff, list, rowBase);
}

// GEMM2: 10 uniform K=2048 slices. z<8 routed; z=8/9 shared halves.
__global__ __launch_bounds__(256, 2)
void moe_gemm2(const float* __restrict__ sb2, const float* __restrict__ eb2)
{
    int z = blockIdx.z;
    int M, ldA;
    const __half *Ah, *Bh;
    const float *bias, *bias2;
    float* Cf;
    if (z < E_NUM) {
        M = g_counts[z];
        Ah = g_hidr + (long)g_base[z] * F_DIM;
        ldA = F_DIM;
        Bh = g_ew2t + (size_t)z * H_DIM * F_DIM;
        bias = eb2 + z * H_DIM; bias2 = nullptr;
        Cf = g_rout + (long)g_base[z] * H_DIM;
    } else if (z == E_NUM) {
        M = T_TOK;
        Ah = g_hids; ldA = F2;
        Bh = g_sw2t;
        bias = sb2; bias2 = sb2 + H_DIM;
        Cf = g_part0;
    } else {
        M = T_TOK;
        Ah = g_hids + F_DIM; ldA = F2;
        Bh = g_sw2t + (size_t)H_DIM * F_DIM;
        bias = g_zb; bias2 = nullptr;
        Cf = g_part1;
    }
    int rowBase = blockIdx.x * 128;
    if (rowBase >= M) return;
    gemm_core<false>(Ah, Bh, bias, bias2, nullptr, Cf,
                     M, F_DIM, ldA, H_DIM, 0, nullptr, rowBase);
}

// ===================== launch =====================
static void* symAddr(const void* sym) { void* p; cudaGetSymbolAddress(&p, sym); return p; }

extern "C" void kernel_launch(void* const* d_in, const int* in_sizes, int n_in,
                              void* d_out, int out_size)
{
    const float* x   = (const float*)d_in[0];
    const float* sw1 = (const float*)d_in[1];
    const float* sb1 = (const float*)d_in[2];
    const float* sw2 = (const float*)d_in[3];
    const float* sb2 = (const float*)d_in[4];
    const float* ew1 = (const float*)d_in[5];
    const float* eb1 = (const float*)d_in[6];
    const float* ew2 = (const float*)d_in[7];
    const float* eb2 = (const float*)d_in[8];
    const float* rw  = (const float*)d_in[9];
    const float* rb  = (const float*)d_in[10];
    float* out = (float*)d_out;

    __half* x_h = (__half*)symAddr(g_x_h);

    cudaFuncSetAttribute(moe_gemm1, cudaFuncAttributeMaxDynamicSharedMemorySize, DSMEM_BYTES);
    cudaFuncSetAttribute(moe_gemm2, cudaFuncAttributeMaxDynamicSharedMemorySize, DSMEM_BYTES);

    // 1
    zero_kernel<<<1, 32>>>();
    // 2
    router_kernel<<<T_TOK / 4, 128>>>(x, rw, rb);
    // 3
    split_kernel<<<(T_TOK * H_DIM / 4 + 255) / 256, 256>>>(x, x_h, T_TOK * H_DIM / 4);
    // 4
    tsplitG1<<<dim3(F_DIM / 32, H_DIM / 32, E_NUM + 2), dim3(32, 8)>>>(sw1, ew1);
    // 5
    base_kernel<<<1, 32>>>();
    // 6: merged GEMM1 (routed + shared)
    moe_gemm1<<<dim3(T_TOK / 128, F_DIM / 128, E_NUM + 2), 256, DSMEM_BYTES>>>(sb1, eb1);
    // 7
    tsplitG2<<<dim3(H_DIM / 32, F_DIM / 32, E_NUM + 2), dim3(32, 8)>>>(sw2, ew2);
    // 8: GEMM2, 10 uniform slices
    moe_gemm2<<<dim3(T_TOK / 128, H_DIM / 128, E_NUM + 2), 256, DSMEM_BYTES>>>(sb2, eb2);
    // 9
    combine_kernel<<<T_TOK, 256>>>(out);
}